// round 6
// baseline (speedup 1.0000x reference)
#include <cuda_runtime.h>

#define NFLAT 4096
#define CH    32
#define CIN   64
#define BATCH 4

// Scratch (allocation-free rule: __device__ globals)
__device__ float gQ[BATCH * CH * NFLAT];   // natural [b][o][hw]; flat == q[b][n][c]
__device__ float gK[BATCH * CH * NFLAT];   // [b][c][m]
__device__ float gV[BATCH * CH * NFLAT];   // flat == v[b][m][c]
__device__ float gY[BATCH * NFLAT * CH];   // [b][n][c]; flat == y2[b][ci][hw]

// ---------------------------------------------------------------------------
// Kernel 1: three 1x1 convs (q, k, v). Output-channel dim split across
// blockIdx.z (16 oc per block) to raise occupancy (was 12%, regs=170).
// ---------------------------------------------------------------------------
__global__ __launch_bounds__(256) void qkv_kernel(
    const float* __restrict__ x,
    const float* __restrict__ w1, const float* __restrict__ b1,
    const float* __restrict__ w2, const float* __restrict__ b2,
    const float* __restrict__ w3, const float* __restrict__ b3)
{
    __shared__ float ws[16 * CIN];
    __shared__ float bs[16];
    int conv = blockIdx.y;
    const float* w    = (conv == 0) ? w1 : (conv == 1) ? w2 : w3;
    const float* bias = (conv == 0) ? b1 : (conv == 1) ? b2 : b3;
    float* o          = (conv == 0) ? gQ : (conv == 1) ? gK : gV;
    int ocb = blockIdx.z * 16;

    int t = threadIdx.x;
    for (int i = t; i < 16 * CIN; i += 256) ws[i] = w[ocb * CIN + i];
    if (t < 16) bs[t] = bias[ocb + t];
    __syncthreads();

    int idx = blockIdx.x * 256 + t;      // (b, hw)
    int b = idx >> 12, hw = idx & 4095;
    const float* xp = x + b * (CIN * NFLAT) + hw;

    float acc[16];
#pragma unroll
    for (int oc = 0; oc < 16; oc++) acc[oc] = bs[oc];

#pragma unroll 8
    for (int c = 0; c < CIN; c++) {
        float xv = xp[c * NFLAT];
#pragma unroll
        for (int oc = 0; oc < 16; oc++) acc[oc] += ws[oc * CIN + c] * xv;
    }

    float* op = o + b * (CH * NFLAT) + ocb * NFLAT + hw;
#pragma unroll
    for (int oc = 0; oc < 16; oc++) op[oc * NFLAT] = acc[oc];
}

// ---------------------------------------------------------------------------
// TF32 split helpers + mma.sync wrapper
// ---------------------------------------------------------------------------
__device__ __forceinline__ void split_tf32(float x, unsigned& hi, unsigned& lo)
{
    unsigned h = __float_as_uint(x) & 0xFFFFE000u;   // keep tf32 mantissa bits
    hi = h;
    lo = __float_as_uint(x - __uint_as_float(h));    // exact residual
}

__device__ __forceinline__ void mma_tf32(float* d, const unsigned* a,
                                         unsigned b0, unsigned b1)
{
    asm volatile(
        "mma.sync.aligned.m16n8k8.row.col.f32.tf32.tf32.f32 "
        "{%0,%1,%2,%3}, {%4,%5,%6,%7}, {%8,%9}, {%0,%1,%2,%3};\n"
        : "+f"(d[0]), "+f"(d[1]), "+f"(d[2]), "+f"(d[3])
        : "r"(a[0]), "r"(a[1]), "r"(a[2]), "r"(a[3]), "r"(b0), "r"(b1));
}

// ---------------------------------------------------------------------------
// Kernel 2: fused QK -> batch-softmax -> PV on tensor cores (3xTF32 split).
// CTA: 32 n-rows for ALL 4 batches; 8 warps = (batch b, 16-row half h).
// m-chunk = 64. K/V/P staged in smem in exact mma fragment order.
// ---------------------------------------------------------------------------
#define KF_OFF 0                    // [4b][8 mt][4 ks][64]   = 8192 floats
#define VF_OFF 8192                 // [4b][4 ct][8 ks][64]   = 8192
#define PF_OFF 16384                // [4b][2 hh][8 ks][128]  = 8192
#define SS_OFF 24576                // [4b][32 li][68]        = 8704
#define SSTR  68
#define SSLAB (32 * SSTR)
#define SM_FLOATS (24576 + 4 * SSLAB)
#define SM_BYTES  (SM_FLOATS * 4)   // 133120 B

__global__ __launch_bounds__(256, 1) void attn_kernel()
{
    extern __shared__ float sm[];
    float* kf = sm + KF_OFF;
    float* vf = sm + VF_OFF;
    float* pf = sm + PF_OFF;
    float* ss = sm + SS_OFF;

    int t    = threadIdx.x;
    int w    = t >> 5;
    int lane = t & 31;
    int g    = lane >> 2;           // groupID
    int tg   = lane & 3;            // threadID in group
    int bb   = w >> 1;              // batch this warp computes
    int hh   = w & 1;               // 16-row half
    int n0   = blockIdx.x * 32;

    // ---- Q fragments: load once, split to tf32 hi/lo, keep in registers ----
    unsigned qhi[4][4], qlo[4][4];
    {
        const float* qb = gQ + bb * (CH * NFLAT) + (n0 + hh * 16) * CH;
#pragma unroll
        for (int ks = 0; ks < 4; ks++) {
            split_tf32(qb[ g      * CH + ks * 8 + tg    ], qhi[ks][0], qlo[ks][0]);
            split_tf32(qb[(g + 8) * CH + ks * 8 + tg    ], qhi[ks][1], qlo[ks][1]);
            split_tf32(qb[ g      * CH + ks * 8 + tg + 4], qhi[ks][2], qlo[ks][2]);
            split_tf32(qb[(g + 8) * CH + ks * 8 + tg + 4], qhi[ks][3], qlo[ks][3]);
        }
    }

    // ---- output accumulators: 16n x 32c per warp = 4 ctiles ----
    float yacc[4][4];
#pragma unroll
    for (int ct = 0; ct < 4; ct++)
#pragma unroll
        for (int r = 0; r < 4; r++) yacc[ct][r] = 0.0f;

    // loader-role constants
    int ldb   = w >> 1;             // batch this warp loads
    int ldh   = w & 1;              // half (16 c-rows for K / 32 m-rows for V)
    // softmax-role constants
    int sli = t >> 3;               // row 0..31
    int smb = (t & 7) * 8;          // 8 consecutive m

    for (int m0 = 0; m0 < NFLAT; m0 += 64) {
        __syncthreads();            // prev chunk fully consumed

        // ---------------- load K chunk into fragment order ----------------
        {
            const float* kg = gK + ldb * (CH * NFLAT) + m0;
            int coff = (lane >> 4);            // 0/1
            int mf   = (lane & 15) * 4;
#pragma unroll
            for (int i = 0; i < 8; i++) {
                int c = ldh * 16 + i * 2 + coff;
                float4 vv = *(const float4*)(kg + c * NFLAT + mf);
                int ks = c >> 3, reg = (c & 7) >> 2, ctg = c & 3;
                const float* pv = (const float*)&vv;
#pragma unroll
                for (int u = 0; u < 4; u++) {
                    int m = mf + u;
                    kf[((ldb * 8 + (m >> 3)) * 4 + ks) * 64 +
                       ((m & 7) * 4 + ctg) * 2 + reg] = pv[u];
                }
            }
        }
        // ---------------- load V chunk into fragment order ----------------
        {
            const float* vg = gV + ldb * (CH * NFLAT) + (m0 + ldh * 32) * CH;
            int moff = lane >> 3;              // 0..3
            int cf   = (lane & 7) * 4;
#pragma unroll
            for (int i = 0; i < 8; i++) {
                int m  = i * 4 + moff;
                float4 vv = *(const float4*)(vg + m * CH + cf);
                int mm = ldh * 32 + m;         // j within chunk 0..63
                int ks = mm >> 3, reg = (mm & 7) >> 2, jtg = mm & 3;
                const float* pv = (const float*)&vv;
#pragma unroll
                for (int u = 0; u < 4; u++) {
                    int c = cf + u;
                    vf[((ldb * 4 + (c >> 3)) * 8 + ks) * 64 +
                       ((c & 7) * 4 + jtg) * 2 + reg] = pv[u];
                }
            }
        }
        __syncthreads();

        // ---------------- QK (split tf32: hi*hi + hi*lo + lo*hi) ----------
        float sacc[8][4];
#pragma unroll
        for (int mt = 0; mt < 8; mt++)
#pragma unroll
            for (int r = 0; r < 4; r++) sacc[mt][r] = 0.0f;

#pragma unroll
        for (int ks = 0; ks < 4; ks++) {
#pragma unroll
            for (int mt = 0; mt < 8; mt++) {
                float2 kv = *(const float2*)(kf + ((bb * 8 + mt) * 4 + ks) * 64 + lane * 2);
                unsigned bh0, bl0, bh1, bl1;
                split_tf32(kv.x, bh0, bl0);
                split_tf32(kv.y, bh1, bl1);
                mma_tf32(sacc[mt], qhi[ks], bh0, bh1);
                mma_tf32(sacc[mt], qhi[ks], bl0, bl1);
                mma_tf32(sacc[mt], qlo[ks], bh0, bh1);
            }
        }
        // store S for softmax
        {
            float* ssb = ss + bb * SSLAB + (hh * 16) * SSTR;
#pragma unroll
            for (int mt = 0; mt < 8; mt++) {
                *(float2*)(ssb +  g      * SSTR + mt * 8 + tg * 2) =
                    make_float2(sacc[mt][0], sacc[mt][1]);
                *(float2*)(ssb + (g + 8) * SSTR + mt * 8 + tg * 2) =
                    make_float2(sacc[mt][2], sacc[mt][3]);
            }
        }
        __syncthreads();

        // ---------------- softmax across the 4 batches --------------------
        {
            float ev[4][8];
#pragma unroll
            for (int b = 0; b < 4; b++) {
                float4 A = *(const float4*)(ss + b * SSLAB + sli * SSTR + smb);
                float4 B = *(const float4*)(ss + b * SSLAB + sli * SSTR + smb + 4);
                ev[b][0] = A.x; ev[b][1] = A.y; ev[b][2] = A.z; ev[b][3] = A.w;
                ev[b][4] = B.x; ev[b][5] = B.y; ev[b][6] = B.z; ev[b][7] = B.w;
            }
            int hh2  = sli >> 4;
            int l15  = sli & 15;
#pragma unroll
            for (int u = 0; u < 8; u++) {
                int m    = smb + u;
                int lane2 = (l15 & 7) * 4 + (m & 3);
                int r     = (l15 >> 3) | (((m >> 2) & 1) << 1);
                int ks    = m >> 3;
                float mx = fmaxf(fmaxf(ev[0][u], ev[1][u]), fmaxf(ev[2][u], ev[3][u]));
                float e0 = __expf(ev[0][u] - mx);
                float e1 = __expf(ev[1][u] - mx);
                float e2 = __expf(ev[2][u] - mx);
                float e3 = __expf(ev[3][u] - mx);
                float inv = 1.0f / (e0 + e1 + e2 + e3);
                pf[((0 * 2 + hh2) * 8 + ks) * 128 + lane2 * 4 + r] = e0 * inv;
                pf[((1 * 2 + hh2) * 8 + ks) * 128 + lane2 * 4 + r] = e1 * inv;
                pf[((2 * 2 + hh2) * 8 + ks) * 128 + lane2 * 4 + r] = e2 * inv;
                pf[((3 * 2 + hh2) * 8 + ks) * 128 + lane2 * 4 + r] = e3 * inv;
            }
        }
        __syncthreads();

        // ---------------- PV (split tf32) ---------------------------------
#pragma unroll
        for (int ks = 0; ks < 8; ks++) {
            float4 p4 = *(const float4*)(pf + ((bb * 2 + hh) * 8 + ks) * 128 + lane * 4);
            unsigned ph[4], pl[4];
            split_tf32(p4.x, ph[0], pl[0]);
            split_tf32(p4.y, ph[1], pl[1]);
            split_tf32(p4.z, ph[2], pl[2]);
            split_tf32(p4.w, ph[3], pl[3]);
#pragma unroll
            for (int ct = 0; ct < 4; ct++) {
                float2 vv = *(const float2*)(vf + ((bb * 4 + ct) * 8 + ks) * 64 + lane * 2);
                unsigned vh0, vl0, vh1, vl1;
                split_tf32(vv.x, vh0, vl0);
                split_tf32(vv.y, vh1, vl1);
                mma_tf32(yacc[ct], ph, vh0, vh1);
                mma_tf32(yacc[ct], ph, vl0, vl1);
                mma_tf32(yacc[ct], pl, vh0, vh1);
            }
        }
    }

    // ---- write y[bb][n][c] ----
    {
        float* yb = gY + bb * (NFLAT * CH) + (n0 + hh * 16) * CH;
#pragma unroll
        for (int ct = 0; ct < 4; ct++) {
            *(float2*)(yb +  g      * CH + ct * 8 + tg * 2) =
                make_float2(yacc[ct][0], yacc[ct][1]);
            *(float2*)(yb + (g + 8) * CH + ct * 8 + tg * 2) =
                make_float2(yacc[ct][2], yacc[ct][3]);
        }
    }
}

// ---------------------------------------------------------------------------
// Kernel 3: final 1x1 conv (32->64). Output channels split across blockIdx.y.
// ---------------------------------------------------------------------------
__global__ __launch_bounds__(256) void outconv_kernel(
    const float* __restrict__ w4, const float* __restrict__ b4,
    float* __restrict__ out)
{
    __shared__ float ws[32 * CH];
    __shared__ float bs[32];
    int t = threadIdx.x;
    int cob = blockIdx.y * 32;
    for (int i = t; i < 32 * CH; i += 256) ws[i] = w4[cob * CH + i];
    if (t < 32) bs[t] = b4[cob + t];
    __syncthreads();

    int idx = blockIdx.x * 256 + t;
    int b = idx >> 12, hw = idx & 4095;
    const float* yp = gY + b * (CH * NFLAT) + hw;   // y2[b][ci][hw]

    float acc[32];
#pragma unroll
    for (int co = 0; co < 32; co++) acc[co] = bs[co];

#pragma unroll 8
    for (int ci = 0; ci < CH; ci++) {
        float yv = yp[ci * NFLAT];
#pragma unroll
        for (int co = 0; co < 32; co++) acc[co] += ws[co * CH + ci] * yv;
    }

    float* op = out + b * (CIN * NFLAT) + cob * NFLAT + hw;
#pragma unroll
    for (int co = 0; co < 32; co++) op[co * NFLAT] = acc[co];
}

// ---------------------------------------------------------------------------
extern "C" void kernel_launch(void* const* d_in, const int* in_sizes, int n_in,
                              void* d_out, int out_size)
{
    const float* x  = (const float*)d_in[0];
    const float* w1 = (const float*)d_in[1];
    const float* b1 = (const float*)d_in[2];
    const float* w2 = (const float*)d_in[3];
    const float* b2 = (const float*)d_in[4];
    const float* w3 = (const float*)d_in[5];
    const float* b3 = (const float*)d_in[6];
    const float* w4 = (const float*)d_in[7];
    const float* b4 = (const float*)d_in[8];
    float* out = (float*)d_out;

    cudaFuncSetAttribute(attn_kernel,
                         cudaFuncAttributeMaxDynamicSharedMemorySize, SM_BYTES);

    qkv_kernel<<<dim3(64, 3, 2), 256>>>(x, w1, b1, w2, b2, w3, b3);
    attn_kernel<<<128, 256, SM_BYTES>>>();
    outconv_kernel<<<dim3(64, 2), 256>>>(w4, b4, out);
}

// round 11
// speedup vs baseline: 3.1525x; 3.1525x over previous
#include <cuda_runtime.h>
#include <cuda_bf16.h>
#include <cstdint>

#define NFLAT 4096
#define CH    32
#define CIN   64
#define BS    (CH * NFLAT)            // 131072 elems per batch

// Scratch (allocation-free rule: __device__ globals)
__device__ __nv_bfloat16 gQh[4 * BS], gQl[4 * BS];  // flat == q[b][n*32+c]
__device__ __nv_bfloat16 gKh[4 * BS], gKl[4 * BS];  // [b][m][c]
__device__ __nv_bfloat16 gVh[4 * BS], gVl[4 * BS];  // flat == v[b][m*32+c]
__device__ float gY[4 * BS];                        // [b][n][c] == y2[b][ci][hw]

// ---------------------------------------------------------------------------
// helpers
// ---------------------------------------------------------------------------
__device__ __forceinline__ uint32_t smem_u32(const void* p) {
    uint32_t a;
    asm("{ .reg .u64 t; cvta.to.shared.u64 t, %1; cvt.u32.u64 %0, t; }"
        : "=r"(a) : "l"(p));
    return a;
}
// pack 2 floats -> bf16x2 (first arg -> low half)
__device__ __forceinline__ uint32_t pk_bf16x2(float lo, float hi) {
    uint32_t r;
    asm("cvt.rn.bf16x2.f32 %0, %1, %2;" : "=r"(r) : "f"(hi), "f"(lo));
    return r;
}
__device__ __forceinline__ void mma16816(float* d, const uint32_t* a,
                                         uint32_t b0, uint32_t b1) {
    asm volatile(
        "mma.sync.aligned.m16n8k16.row.col.f32.bf16.bf16.f32 "
        "{%0,%1,%2,%3}, {%4,%5,%6,%7}, {%8,%9}, {%0,%1,%2,%3};"
        : "+f"(d[0]), "+f"(d[1]), "+f"(d[2]), "+f"(d[3])
        : "r"(a[0]), "r"(a[1]), "r"(a[2]), "r"(a[3]), "r"(b0), "r"(b1));
}
__device__ __forceinline__ void ldsm4(uint32_t* r, uint32_t a) {
    asm volatile("ldmatrix.sync.aligned.m8n8.x4.shared.b16 {%0,%1,%2,%3}, [%4];"
        : "=r"(r[0]), "=r"(r[1]), "=r"(r[2]), "=r"(r[3]) : "r"(a));
}
__device__ __forceinline__ void ldsm4t(uint32_t* r, uint32_t a) {
    asm volatile("ldmatrix.sync.aligned.m8n8.x4.trans.shared.b16 {%0,%1,%2,%3}, [%4];"
        : "=r"(r[0]), "=r"(r[1]), "=r"(r[2]), "=r"(r[3]) : "r"(a));
}

// ---------------------------------------------------------------------------
// Kernel 1: three 1x1 convs -> bf16 hi/lo operand buffers.
// Q (conv0) natural [oc][hw] == q[n][c] flat; K (conv1) -> [m][c]; V (conv2)
// natural == v[m][c] flat.
// ---------------------------------------------------------------------------
__global__ __launch_bounds__(256) void qkv_kernel(
    const float* __restrict__ x,
    const float* __restrict__ w1, const float* __restrict__ b1,
    const float* __restrict__ w2, const float* __restrict__ b2,
    const float* __restrict__ w3, const float* __restrict__ b3)
{
    __shared__ float ws[16 * CIN];
    __shared__ float bsm[16];
    int conv = blockIdx.y;
    const float* w    = (conv == 0) ? w1 : (conv == 1) ? w2 : w3;
    const float* bias = (conv == 0) ? b1 : (conv == 1) ? b2 : b3;
    int ocb = blockIdx.z * 16;

    int t = threadIdx.x;
    for (int i = t; i < 16 * CIN; i += 256) ws[i] = w[ocb * CIN + i];
    if (t < 16) bsm[t] = bias[ocb + t];
    __syncthreads();

    int idx = blockIdx.x * 256 + t;
    int b = idx >> 12, hw = idx & 4095;
    const float* xp = x + b * (CIN * NFLAT) + hw;

    float acc[16];
#pragma unroll
    for (int oc = 0; oc < 16; oc++) acc[oc] = bsm[oc];
#pragma unroll 8
    for (int c = 0; c < CIN; c++) {
        float xv = xp[c * NFLAT];
#pragma unroll
        for (int oc = 0; oc < 16; oc++) acc[oc] += ws[oc * CIN + c] * xv;
    }

    if (conv != 1) {                    // Q or V: natural strided bf16
        __nv_bfloat16* oh = (conv == 0 ? gQh : gVh) + b * BS + ocb * NFLAT + hw;
        __nv_bfloat16* ol = (conv == 0 ? gQl : gVl) + b * BS + ocb * NFLAT + hw;
#pragma unroll
        for (int oc = 0; oc < 16; oc++) {
            float a = acc[oc];
            __nv_bfloat16 h = __float2bfloat16(a);
            oh[oc * NFLAT] = h;
            ol[oc * NFLAT] = __float2bfloat16(a - __bfloat162float(h));
        }
    } else {                            // K: [m][c] contiguous 16 channels
        uint32_t hp[8], lp[8];
#pragma unroll
        for (int j = 0; j < 8; j++) {
            float a0 = acc[2*j], a1 = acc[2*j+1];
            uint32_t h = pk_bf16x2(a0, a1);
            hp[j] = h;
            float r0 = a0 - __uint_as_float(h << 16);
            float r1 = a1 - __uint_as_float(h & 0xFFFF0000u);
            lp[j] = pk_bf16x2(r0, r1);
        }
        __nv_bfloat16* kh = gKh + b * BS + hw * CH + ocb;
        __nv_bfloat16* kl = gKl + b * BS + hw * CH + ocb;
        *(uint4*)kh       = make_uint4(hp[0], hp[1], hp[2], hp[3]);
        *(uint4*)(kh + 8) = make_uint4(hp[4], hp[5], hp[6], hp[7]);
        *(uint4*)kl       = make_uint4(lp[0], lp[1], lp[2], lp[3]);
        *(uint4*)(kl + 8) = make_uint4(lp[4], lp[5], lp[6], lp[7]);
    }
}

// ---------------------------------------------------------------------------
// Kernel 2: fused QK -> batch-softmax -> PV on mma.sync bf16 (3-term split).
// CTA = 32 n rows x all 4 batches x full 4096 m (64 chunks of 64).
// 8 warps = 2 n-subtiles x 4 m-subtiles; softmax entirely in registers.
// Cross-wm partial-Y reduction via smem at the end (the R9 fix).
// smem rows padded to 80B (ldmatrix conflict-free). cp.async double buffer.
// ---------------------------------------------------------------------------
#define QS  0
#define KSO 20480
#define VSO 102400
#define STG 40960
#define SMB 184320

__device__ __forceinline__ void stage_kv(uint32_t sb, int t, int m0, int stg)
{
#pragma unroll
    for (int i = 0; i < 8; i++) {
        int idx = t + 256 * i;
        int chk = idx & 3, row = (idx >> 2) & 63, hl = (idx >> 8) & 1, b = (idx >> 9) & 3;
        int goff = b * BS + (m0 + row) * CH + chk * 8;
        uint32_t soff = (uint32_t)((b * 2 + hl) * 5120 + row * 80 + chk * 16);
        const __nv_bfloat16* kp = (hl ? gKl : gKh) + goff;
        const __nv_bfloat16* vp = (hl ? gVl : gVh) + goff;
        uint32_t ka = sb + KSO + stg + soff;
        uint32_t va = sb + VSO + stg + soff;
        asm volatile("cp.async.cg.shared.global [%0], [%1], 16;" :: "r"(ka), "l"(kp) : "memory");
        asm volatile("cp.async.cg.shared.global [%0], [%1], 16;" :: "r"(va), "l"(vp) : "memory");
    }
    asm volatile("cp.async.commit_group;" ::: "memory");
}

__global__ __launch_bounds__(256, 1) void attn_kernel()
{
    extern __shared__ char smc[];
    uint32_t sb = smem_u32(smc);
    int t = threadIdx.x, w = t >> 5, l = t & 31;
    int g = l >> 2, tg = l & 3;
    int wn = w >> 2, wm = w & 3;
    int n0 = blockIdx.x * 32;

    // ---- stage Q tiles (once): [b][hl][32 rows][40 bf16(pad)] ----
#pragma unroll
    for (int i = 0; i < 4; i++) {
        int idx = t + 256 * i;
        int chk = idx & 3, row = (idx >> 2) & 31, hl = (idx >> 7) & 1, b = (idx >> 8) & 3;
        const __nv_bfloat16* src = (hl ? gQl : gQh) + b * BS + (n0 + row) * CH + chk * 8;
        *(uint4*)(smc + QS + (b * 2 + hl) * 2560 + row * 80 + chk * 16) =
            *(const uint4*)src;
    }

    // ldmatrix lane geometry (submatrix order == fragment reg order)
    int lr = l & 7, sub = l >> 3, subr = sub & 1, subc = sub >> 1;
    uint32_t rpq = (uint32_t)((wn * 16 + lr + subr * 8) * 80 + subc * 16);
    uint32_t rpk = (uint32_t)((wm * 16 + lr + subr * 8) * 80 + subc * 16);

    float Y[4][4][4];
#pragma unroll
    for (int b = 0; b < 4; b++)
#pragma unroll
        for (int cg = 0; cg < 4; cg++)
#pragma unroll
            for (int r = 0; r < 4; r++) Y[b][cg][r] = 0.0f;

    stage_kv(sb, t, 0, 0);              // prologue: chunk 0

    for (int c = 0; c < 64; c++) {
        asm volatile("cp.async.wait_group 0;" ::: "memory");
        __syncthreads();
        if (c < 63) stage_kv(sb, t, (c + 1) * 64, ((c + 1) & 1) * STG);
        uint32_t sbK = sb + KSO + (c & 1) * STG;
        uint32_t sbV = sb + VSO + (c & 1) * STG;
        uint32_t sbQ = sb + QS;

        // ---------------- QK: S_b = Q_b K_b^T (hh + hl + lh) ----------------
        float S[4][2][4];
#pragma unroll
        for (int b = 0; b < 4; b++) {
            uint32_t qh[2][4], ql[2][4], kh[2][4], kl[2][4];
            uint32_t qb = sbQ + (b * 2) * 2560 + rpq;
            ldsm4(qh[0], qb);           ldsm4(qh[1], qb + 32);
            ldsm4(ql[0], qb + 2560);    ldsm4(ql[1], qb + 2560 + 32);
            uint32_t kb = sbK + (b * 2) * 5120 + rpk;
            ldsm4(kh[0], kb);           ldsm4(kh[1], kb + 32);
            ldsm4(kl[0], kb + 5120);    ldsm4(kl[1], kb + 5120 + 32);
#pragma unroll
            for (int mg = 0; mg < 2; mg++)
#pragma unroll
                for (int r = 0; r < 4; r++) S[b][mg][r] = 0.0f;
#pragma unroll
            for (int kg = 0; kg < 2; kg++) {
                mma16816(S[b][0], qh[kg], kh[kg][0], kh[kg][2]);
                mma16816(S[b][1], qh[kg], kh[kg][1], kh[kg][3]);
                mma16816(S[b][0], qh[kg], kl[kg][0], kl[kg][2]);
                mma16816(S[b][1], qh[kg], kl[kg][1], kl[kg][3]);
                mma16816(S[b][0], ql[kg], kh[kg][0], kh[kg][2]);
                mma16816(S[b][1], ql[kg], kh[kg][1], kh[kg][3]);
            }
        }

        // ------- softmax over batch (pointwise), pack P as A-frags ---------
        uint32_t pH[4][4], pL[4][4];
#pragma unroll
        for (int mg = 0; mg < 2; mg++)
#pragma unroll
            for (int rp = 0; rp < 2; rp++) {
                int a = mg * 2 + rp;
                float e0[4], e1[4], s0 = 0.f, s1 = 0.f;
#pragma unroll
                for (int b = 0; b < 4; b++) {
                    e0[b] = __expf(S[b][mg][rp * 2]);     s0 += e0[b];
                    e1[b] = __expf(S[b][mg][rp * 2 + 1]); s1 += e1[b];
                }
                float i0 = __fdividef(1.f, s0), i1 = __fdividef(1.f, s1);
#pragma unroll
                for (int b = 0; b < 4; b++) {
                    float p0 = e0[b] * i0, p1 = e1[b] * i1;
                    uint32_t hp = pk_bf16x2(p0, p1);
                    float r0 = p0 - __uint_as_float(hp << 16);
                    float r1 = p1 - __uint_as_float(hp & 0xFFFF0000u);
                    pH[b][a] = hp;
                    pL[b][a] = pk_bf16x2(r0, r1);
                }
            }

        // ---------------- PV: Y_b += P_b V_b (hh + hl + lh) ----------------
#pragma unroll
        for (int b = 0; b < 4; b++) {
            uint32_t vh[2][4], vl[2][4];
            uint32_t vb = sbV + (b * 2) * 5120 + rpk;
            ldsm4t(vh[0], vb);          ldsm4t(vh[1], vb + 32);
            ldsm4t(vl[0], vb + 5120);   ldsm4t(vl[1], vb + 5120 + 32);
#pragma unroll
            for (int cg = 0; cg < 4; cg++) {
                uint32_t bh0 = vh[cg >> 1][(cg & 1) * 2];
                uint32_t bh1 = vh[cg >> 1][(cg & 1) * 2 + 1];
                uint32_t bl0 = vl[cg >> 1][(cg & 1) * 2];
                uint32_t bl1 = vl[cg >> 1][(cg & 1) * 2 + 1];
                mma16816(Y[b][cg], pH[b], bh0, bh1);
                mma16816(Y[b][cg], pH[b], bl0, bl1);
                mma16816(Y[b][cg], pL[b], bh0, bh1);
            }
        }
    }

    // ---- cross-wm reduction of partial Y (the R9 fix), then write ----
    __syncthreads();                    // all warps done reading K/V smem
    float* red = (float*)smc;           // 8w x 64e x 32 lanes = 64 KB
#pragma unroll
    for (int b = 0; b < 4; b++)
#pragma unroll
        for (int cg = 0; cg < 4; cg++)
#pragma unroll
            for (int r = 0; r < 4; r++)
                red[(w * 64 + b * 16 + cg * 4 + r) * 32 + l] = Y[b][cg][r];
    __syncthreads();
    {
        int b = wm;                     // warp (wn,wm) reduces batch wm
        float o[16];
#pragma unroll
        for (int cg = 0; cg < 4; cg++)
#pragma unroll
            for (int r = 0; r < 4; r++) {
                int e = b * 16 + cg * 4 + r;
                o[cg * 4 + r] =
                      red[((wn * 4 + 0) * 64 + e) * 32 + l]
                    + red[((wn * 4 + 1) * 64 + e) * 32 + l]
                    + red[((wn * 4 + 2) * 64 + e) * 32 + l]
                    + red[((wn * 4 + 3) * 64 + e) * 32 + l];
            }
        int n = n0 + wn * 16 + g;
#pragma unroll
        for (int cg = 0; cg < 4; cg++) {
            int cc = cg * 8 + tg * 2;
            *(float2*)(gY + b * BS + n * CH + cc) =
                make_float2(o[cg * 4 + 0], o[cg * 4 + 1]);
            *(float2*)(gY + b * BS + (n + 8) * CH + cc) =
                make_float2(o[cg * 4 + 2], o[cg * 4 + 3]);
        }
    }
}

// ---------------------------------------------------------------------------
// Kernel 3: final 1x1 conv (32->64). gY flat == y2[b][ci][hw].
// ---------------------------------------------------------------------------
__global__ __launch_bounds__(256) void outconv_kernel(
    const float* __restrict__ w4, const float* __restrict__ b4,
    float* __restrict__ out)
{
    __shared__ float ws[32 * CH];
    __shared__ float bsm[32];
    int t = threadIdx.x;
    int cob = blockIdx.y * 32;
    for (int i = t; i < 32 * CH; i += 256) ws[i] = w4[cob * CH + i];
    if (t < 32) bsm[t] = b4[cob + t];
    __syncthreads();

    int idx = blockIdx.x * 256 + t;
    int b = idx >> 12, hw = idx & 4095;
    const float* yp = gY + b * BS + hw;

    float acc[32];
#pragma unroll
    for (int co = 0; co < 32; co++) acc[co] = bsm[co];

#pragma unroll 8
    for (int ci = 0; ci < CH; ci++) {
        float yv = yp[ci * NFLAT];
#pragma unroll
        for (int co = 0; co < 32; co++) acc[co] += ws[co * CH + ci] * yv;
    }

    float* op = out + b * (CIN * NFLAT) + cob * NFLAT + hw;
#pragma unroll
    for (int co = 0; co < 32; co++) op[co * NFLAT] = acc[co];
}

// ---------------------------------------------------------------------------
extern "C" void kernel_launch(void* const* d_in, const int* in_sizes, int n_in,
                              void* d_out, int out_size)
{
    const float* x  = (const float*)d_in[0];
    const float* w1 = (const float*)d_in[1];
    const float* b1 = (const float*)d_in[2];
    const float* w2 = (const float*)d_in[3];
    const float* b2 = (const float*)d_in[4];
    const float* w3 = (const float*)d_in[5];
    const float* b3 = (const float*)d_in[6];
    const float* w4 = (const float*)d_in[7];
    const float* b4 = (const float*)d_in[8];
    float* out = (float*)d_out;

    cudaFuncSetAttribute(attn_kernel,
                         cudaFuncAttributeMaxDynamicSharedMemorySize, SMB);

    qkv_kernel<<<dim3(64, 3, 2), 256>>>(x, w1, b1, w2, b2, w3, b3);
    attn_kernel<<<128, 256, SMB>>>();
    outconv_kernel<<<dim3(64, 2), 256>>>(w4, b4, out);
}

// round 12
// speedup vs baseline: 3.3241x; 1.0544x over previous
#include <cuda_runtime.h>
#include <cuda_fp16.h>
#include <cstdint>

#define NFLAT 4096
#define CH    32
#define CIN   64
#define BS    (CH * NFLAT)            // 131072 elems per batch

// Scratch (allocation-free rule: __device__ globals)
__device__ __half gQh[4 * BS], gQl[4 * BS];  // flat == q[b][n*32+c]
__device__ __half gKh[4 * BS], gKl[4 * BS];  // [b][m][c]
__device__ __half gVh[4 * BS], gVl[4 * BS];  // flat == v[b][m*32+c]
__device__ float gY[4 * BS];                 // [b][n][c] == y2[b][ci][hw]

// ---------------------------------------------------------------------------
// helpers
// ---------------------------------------------------------------------------
__device__ __forceinline__ uint32_t smem_u32(const void* p) {
    uint32_t a;
    asm("{ .reg .u64 t; cvta.to.shared.u64 t, %1; cvt.u32.u64 %0, t; }"
        : "=r"(a) : "l"(p));
    return a;
}
// pack 2 floats -> f16x2 (first arg -> low half)
__device__ __forceinline__ uint32_t pk_f16x2(float lo, float hi) {
    uint32_t r;
    asm("cvt.rn.f16x2.f32 %0, %1, %2;" : "=r"(r) : "f"(hi), "f"(lo));
    return r;
}
__device__ __forceinline__ void mma16816(float* d, const uint32_t* a,
                                         uint32_t b0, uint32_t b1) {
    asm volatile(
        "mma.sync.aligned.m16n8k16.row.col.f32.f16.f16.f32 "
        "{%0,%1,%2,%3}, {%4,%5,%6,%7}, {%8,%9}, {%0,%1,%2,%3};"
        : "+f"(d[0]), "+f"(d[1]), "+f"(d[2]), "+f"(d[3])
        : "r"(a[0]), "r"(a[1]), "r"(a[2]), "r"(a[3]), "r"(b0), "r"(b1));
}
__device__ __forceinline__ void ldsm4(uint32_t* r, uint32_t a) {
    asm volatile("ldmatrix.sync.aligned.m8n8.x4.shared.b16 {%0,%1,%2,%3}, [%4];"
        : "=r"(r[0]), "=r"(r[1]), "=r"(r[2]), "=r"(r[3]) : "r"(a));
}
__device__ __forceinline__ void ldsm4t(uint32_t* r, uint32_t a) {
    asm volatile("ldmatrix.sync.aligned.m8n8.x4.trans.shared.b16 {%0,%1,%2,%3}, [%4];"
        : "=r"(r[0]), "=r"(r[1]), "=r"(r[2]), "=r"(r[3]) : "r"(a));
}

// ---------------------------------------------------------------------------
// Kernel 1: three 1x1 convs -> fp16 hi/lo operand buffers.
// Q (conv0) natural [oc][hw] == q[n][c] flat; K (conv1) -> [m][c]; V (conv2)
// natural == v[m][c] flat.
// ---------------------------------------------------------------------------
__global__ __launch_bounds__(256) void qkv_kernel(
    const float* __restrict__ x,
    const float* __restrict__ w1, const float* __restrict__ b1,
    const float* __restrict__ w2, const float* __restrict__ b2,
    const float* __restrict__ w3, const float* __restrict__ b3)
{
    __shared__ float ws[16 * CIN];
    __shared__ float bsm[16];
    int conv = blockIdx.y;
    const float* w    = (conv == 0) ? w1 : (conv == 1) ? w2 : w3;
    const float* bias = (conv == 0) ? b1 : (conv == 1) ? b2 : b3;
    int ocb = blockIdx.z * 16;

    int t = threadIdx.x;
    for (int i = t; i < 16 * CIN; i += 256) ws[i] = w[ocb * CIN + i];
    if (t < 16) bsm[t] = bias[ocb + t];
    __syncthreads();

    int idx = blockIdx.x * 256 + t;
    int b = idx >> 12, hw = idx & 4095;
    const float* xp = x + b * (CIN * NFLAT) + hw;

    float acc[16];
#pragma unroll
    for (int oc = 0; oc < 16; oc++) acc[oc] = bsm[oc];
#pragma unroll 8
    for (int c = 0; c < CIN; c++) {
        float xv = xp[c * NFLAT];
#pragma unroll
        for (int oc = 0; oc < 16; oc++) acc[oc] += ws[oc * CIN + c] * xv;
    }

    if (conv != 1) {                    // Q or V: natural strided fp16
        __half* oh = (conv == 0 ? gQh : gVh) + b * BS + ocb * NFLAT + hw;
        __half* ol = (conv == 0 ? gQl : gVl) + b * BS + ocb * NFLAT + hw;
#pragma unroll
        for (int oc = 0; oc < 16; oc++) {
            float a = acc[oc];
            __half h = __float2half_rn(a);
            oh[oc * NFLAT] = h;
            ol[oc * NFLAT] = __float2half_rn(a - __half2float(h));
        }
    } else {                            // K: [m][c] contiguous 16 channels
        uint32_t hp[8], lp[8];
#pragma unroll
        for (int j = 0; j < 8; j++) {
            float a0 = acc[2*j], a1 = acc[2*j+1];
            __half h0 = __float2half_rn(a0), h1 = __float2half_rn(a1);
            float r0 = a0 - __half2float(h0);
            float r1 = a1 - __half2float(h1);
            __half l0 = __float2half_rn(r0), l1 = __float2half_rn(r1);
            hp[j] = ((uint32_t)__half_as_ushort(h1) << 16) | __half_as_ushort(h0);
            lp[j] = ((uint32_t)__half_as_ushort(l1) << 16) | __half_as_ushort(l0);
        }
        __half* kh = gKh + b * BS + hw * CH + ocb;
        __half* kl = gKl + b * BS + hw * CH + ocb;
        *(uint4*)kh       = make_uint4(hp[0], hp[1], hp[2], hp[3]);
        *(uint4*)(kh + 8) = make_uint4(hp[4], hp[5], hp[6], hp[7]);
        *(uint4*)kl       = make_uint4(lp[0], lp[1], lp[2], lp[3]);
        *(uint4*)(kl + 8) = make_uint4(lp[4], lp[5], lp[6], lp[7]);
    }
}

// ---------------------------------------------------------------------------
// Kernel 2: fused QK -> batch-softmax -> PV on mma.sync fp16.
// QK: 3-term split (hh+hl+lh).  PV: 2-term (Ph*Vh + Ph*Vl), P rounded once.
// CTA = 32 n rows x all 4 batches x full 4096 m (64 chunks of 64).
// 8 warps = 2 n-subtiles x 4 m-subtiles; softmax entirely in registers.
// Cross-wm partial-Y reduction via smem at the end.
// smem rows padded to 80B (ldmatrix conflict-free). cp.async double buffer.
// ---------------------------------------------------------------------------
#define QS  0
#define KSO 20480
#define VSO 102400
#define STG 40960
#define SMB 184320

__device__ __forceinline__ void stage_kv(uint32_t sb, int t, int m0, int stg)
{
#pragma unroll
    for (int i = 0; i < 8; i++) {
        int idx = t + 256 * i;
        int chk = idx & 3, row = (idx >> 2) & 63, hl = (idx >> 8) & 1, b = (idx >> 9) & 3;
        int goff = b * BS + (m0 + row) * CH + chk * 8;
        uint32_t soff = (uint32_t)((b * 2 + hl) * 5120 + row * 80 + chk * 16);
        const __half* kp = (hl ? gKl : gKh) + goff;
        const __half* vp = (hl ? gVl : gVh) + goff;
        uint32_t ka = sb + KSO + stg + soff;
        uint32_t va = sb + VSO + stg + soff;
        asm volatile("cp.async.cg.shared.global [%0], [%1], 16;" :: "r"(ka), "l"(kp) : "memory");
        asm volatile("cp.async.cg.shared.global [%0], [%1], 16;" :: "r"(va), "l"(vp) : "memory");
    }
    asm volatile("cp.async.commit_group;" ::: "memory");
}

__global__ __launch_bounds__(256, 1) void attn_kernel()
{
    extern __shared__ char smc[];
    uint32_t sb = smem_u32(smc);
    int t = threadIdx.x, w = t >> 5, l = t & 31;
    int g = l >> 2, tg = l & 3;
    int wn = w >> 2, wm = w & 3;
    int n0 = blockIdx.x * 32;

    // ---- stage Q tiles (once): [b][hl][32 rows][40 halves(pad)] ----
#pragma unroll
    for (int i = 0; i < 4; i++) {
        int idx = t + 256 * i;
        int chk = idx & 3, row = (idx >> 2) & 31, hl = (idx >> 7) & 1, b = (idx >> 8) & 3;
        const __half* src = (hl ? gQl : gQh) + b * BS + (n0 + row) * CH + chk * 8;
        *(uint4*)(smc + QS + (b * 2 + hl) * 2560 + row * 80 + chk * 16) =
            *(const uint4*)src;
    }

    // ldmatrix lane geometry (submatrix order == fragment reg order)
    int lr = l & 7, sub = l >> 3, subr = sub & 1, subc = sub >> 1;
    uint32_t rpq = (uint32_t)((wn * 16 + lr + subr * 8) * 80 + subc * 16);
    uint32_t rpk = (uint32_t)((wm * 16 + lr + subr * 8) * 80 + subc * 16);

    float Y[4][4][4];
#pragma unroll
    for (int b = 0; b < 4; b++)
#pragma unroll
        for (int cg = 0; cg < 4; cg++)
#pragma unroll
            for (int r = 0; r < 4; r++) Y[b][cg][r] = 0.0f;

    stage_kv(sb, t, 0, 0);              // prologue: chunk 0

    for (int c = 0; c < 64; c++) {
        asm volatile("cp.async.wait_group 0;" ::: "memory");
        __syncthreads();
        if (c < 63) stage_kv(sb, t, (c + 1) * 64, ((c + 1) & 1) * STG);
        uint32_t sbK = sb + KSO + (c & 1) * STG;
        uint32_t sbV = sb + VSO + (c & 1) * STG;
        uint32_t sbQ = sb + QS;

        // ---------------- QK: S_b = Q_b K_b^T (hh + hl + lh) ----------------
        float S[4][2][4];
#pragma unroll
        for (int b = 0; b < 4; b++) {
            uint32_t qh[2][4], ql[2][4], kh[2][4], kl[2][4];
            uint32_t qb = sbQ + (b * 2) * 2560 + rpq;
            ldsm4(qh[0], qb);           ldsm4(qh[1], qb + 32);
            ldsm4(ql[0], qb + 2560);    ldsm4(ql[1], qb + 2560 + 32);
            uint32_t kb = sbK + (b * 2) * 5120 + rpk;
            ldsm4(kh[0], kb);           ldsm4(kh[1], kb + 32);
            ldsm4(kl[0], kb + 5120);    ldsm4(kl[1], kb + 5120 + 32);
#pragma unroll
            for (int mg = 0; mg < 2; mg++)
#pragma unroll
                for (int r = 0; r < 4; r++) S[b][mg][r] = 0.0f;
#pragma unroll
            for (int kg = 0; kg < 2; kg++) {
                mma16816(S[b][0], qh[kg], kh[kg][0], kh[kg][2]);
                mma16816(S[b][1], qh[kg], kh[kg][1], kh[kg][3]);
                mma16816(S[b][0], qh[kg], kl[kg][0], kl[kg][2]);
                mma16816(S[b][1], qh[kg], kl[kg][1], kl[kg][3]);
                mma16816(S[b][0], ql[kg], kh[kg][0], kh[kg][2]);
                mma16816(S[b][1], ql[kg], kh[kg][1], kh[kg][3]);
            }
        }

        // ------- softmax over batch (pointwise), pack P once as fp16 -------
        uint32_t pH[4][4];
#pragma unroll
        for (int mg = 0; mg < 2; mg++)
#pragma unroll
            for (int rp = 0; rp < 2; rp++) {
                int a = mg * 2 + rp;
                float e0[4], e1[4], s0 = 0.f, s1 = 0.f;
#pragma unroll
                for (int b = 0; b < 4; b++) {
                    e0[b] = __expf(S[b][mg][rp * 2]);     s0 += e0[b];
                    e1[b] = __expf(S[b][mg][rp * 2 + 1]); s1 += e1[b];
                }
                float i0 = __fdividef(1.f, s0), i1 = __fdividef(1.f, s1);
#pragma unroll
                for (int b = 0; b < 4; b++)
                    pH[b][a] = pk_f16x2(e0[b] * i0, e1[b] * i1);
            }

        // ---------------- PV: Y_b += Ph_b (Vh_b + Vl_b) --------------------
#pragma unroll
        for (int b = 0; b < 4; b++) {
            uint32_t vh[2][4], vl[2][4];
            uint32_t vb = sbV + (b * 2) * 5120 + rpk;
            ldsm4t(vh[0], vb);          ldsm4t(vh[1], vb + 32);
            ldsm4t(vl[0], vb + 5120);   ldsm4t(vl[1], vb + 5120 + 32);
#pragma unroll
            for (int cg = 0; cg < 4; cg++) {
                uint32_t bh0 = vh[cg >> 1][(cg & 1) * 2];
                uint32_t bh1 = vh[cg >> 1][(cg & 1) * 2 + 1];
                uint32_t bl0 = vl[cg >> 1][(cg & 1) * 2];
                uint32_t bl1 = vl[cg >> 1][(cg & 1) * 2 + 1];
                mma16816(Y[b][cg], pH[b], bh0, bh1);
                mma16816(Y[b][cg], pH[b], bl0, bl1);
            }
        }
    }

    // ---- cross-wm reduction of partial Y, then write ----
    __syncthreads();                    // all warps done reading K/V smem
    float* red = (float*)smc;           // 8w x 64e x 32 lanes = 64 KB
#pragma unroll
    for (int b = 0; b < 4; b++)
#pragma unroll
        for (int cg = 0; cg < 4; cg++)
#pragma unroll
            for (int r = 0; r < 4; r++)
                red[(w * 64 + b * 16 + cg * 4 + r) * 32 + l] = Y[b][cg][r];
    __syncthreads();
    {
        int b = wm;                     // warp (wn,wm) reduces batch wm
        float o[16];
#pragma unroll
        for (int cg = 0; cg < 4; cg++)
#pragma unroll
            for (int r = 0; r < 4; r++) {
                int e = b * 16 + cg * 4 + r;
                o[cg * 4 + r] =
                      red[((wn * 4 + 0) * 64 + e) * 32 + l]
                    + red[((wn * 4 + 1) * 64 + e) * 32 + l]
                    + red[((wn * 4 + 2) * 64 + e) * 32 + l]
                    + red[((wn * 4 + 3) * 64 + e) * 32 + l];
            }
        int n = n0 + wn * 16 + g;
#pragma unroll
        for (int cg = 0; cg < 4; cg++) {
            int cc = cg * 8 + tg * 2;
            *(float2*)(gY + b * BS + n * CH + cc) =
                make_float2(o[cg * 4 + 0], o[cg * 4 + 1]);
            *(float2*)(gY + b * BS + (n + 8) * CH + cc) =
                make_float2(o[cg * 4 + 2], o[cg * 4 + 3]);
        }
    }
}

// ---------------------------------------------------------------------------
// Kernel 3: final 1x1 conv (32->64). gY flat == y2[b][ci][hw].
// ---------------------------------------------------------------------------
__global__ __launch_bounds__(256) void outconv_kernel(
    const float* __restrict__ w4, const float* __restrict__ b4,
    float* __restrict__ out)
{
    __shared__ float ws[32 * CH];
    __shared__ float bsm[32];
    int t = threadIdx.x;
    int cob = blockIdx.y * 32;
    for (int i = t; i < 32 * CH; i += 256) ws[i] = w4[cob * CH + i];
    if (t < 32) bsm[t] = b4[cob + t];
    __syncthreads();

    int idx = blockIdx.x * 256 + t;
    int b = idx >> 12, hw = idx & 4095;
    const float* yp = gY + b * BS + hw;

    float acc[32];
#pragma unroll
    for (int co = 0; co < 32; co++) acc[co] = bsm[co];

#pragma unroll 8
    for (int ci = 0; ci < CH; ci++) {
        float yv = yp[ci * NFLAT];
#pragma unroll
        for (int co = 0; co < 32; co++) acc[co] += ws[co * CH + ci] * yv;
    }

    float* op = out + b * (CIN * NFLAT) + cob * NFLAT + hw;
#pragma unroll
    for (int co = 0; co < 32; co++) op[co * NFLAT] = acc[co];
}

// ---------------------------------------------------------------------------
extern "C" void kernel_launch(void* const* d_in, const int* in_sizes, int n_in,
                              void* d_out, int out_size)
{
    const float* x  = (const float*)d_in[0];
    const float* w1 = (const float*)d_in[1];
    const float* b1 = (const float*)d_in[2];
    const float* w2 = (const float*)d_in[3];
    const float* b2 = (const float*)d_in[4];
    const float* w3 = (const float*)d_in[5];
    const float* b3 = (const float*)d_in[6];
    const float* w4 = (const float*)d_in[7];
    const float* b4 = (const float*)d_in[8];
    float* out = (float*)d_out;

    cudaFuncSetAttribute(attn_kernel,
                         cudaFuncAttributeMaxDynamicSharedMemorySize, SMB);

    qkv_kernel<<<dim3(64, 3, 2), 256>>>(x, w1, b1, w2, b2, w3, b3);
    attn_kernel<<<128, 256, SMB>>>();
    outconv_kernel<<<dim3(64, 2), 256>>>(w4, b4, out);
}

// round 13
// speedup vs baseline: 3.4769x; 1.0460x over previous
#include <cuda_runtime.h>
#include <cuda_fp16.h>
#include <cstdint>

#define NFLAT 4096
#define CH    32
#define CIN   64
#define BS    (CH * NFLAT)            // 131072 elems per batch

// Scratch (allocation-free rule: __device__ globals)
__device__ __half gQh[4 * BS], gQl[4 * BS];  // flat == q[b][n*32+c]
__device__ __half gKh[4 * BS], gKl[4 * BS];  // [b][m][c]
__device__ __half gVh[4 * BS], gVl[4 * BS];  // flat == v[b][m*32+c]
__device__ float gY[4 * BS];                 // [b][n][c] == y2[b][ci][hw]

// ---------------------------------------------------------------------------
// helpers
// ---------------------------------------------------------------------------
__device__ __forceinline__ uint32_t smem_u32(const void* p) {
    uint32_t a;
    asm("{ .reg .u64 t; cvta.to.shared.u64 t, %1; cvt.u32.u64 %0, t; }"
        : "=r"(a) : "l"(p));
    return a;
}
// pack 2 floats -> f16x2 (first arg -> low half)
__device__ __forceinline__ uint32_t pk_f16x2(float lo, float hi) {
    uint32_t r;
    asm("cvt.rn.f16x2.f32 %0, %1, %2;" : "=r"(r) : "f"(hi), "f"(lo));
    return r;
}
__device__ __forceinline__ void mma16816(float* d, const uint32_t* a,
                                         uint32_t b0, uint32_t b1) {
    asm volatile(
        "mma.sync.aligned.m16n8k16.row.col.f32.f16.f16.f32 "
        "{%0,%1,%2,%3}, {%4,%5,%6,%7}, {%8,%9}, {%0,%1,%2,%3};"
        : "+f"(d[0]), "+f"(d[1]), "+f"(d[2]), "+f"(d[3])
        : "r"(a[0]), "r"(a[1]), "r"(a[2]), "r"(a[3]), "r"(b0), "r"(b1));
}
__device__ __forceinline__ void ldsm4(uint32_t* r, uint32_t a) {
    asm volatile("ldmatrix.sync.aligned.m8n8.x4.shared.b16 {%0,%1,%2,%3}, [%4];"
        : "=r"(r[0]), "=r"(r[1]), "=r"(r[2]), "=r"(r[3]) : "r"(a));
}
__device__ __forceinline__ void ldsm4t(uint32_t* r, uint32_t a) {
    asm volatile("ldmatrix.sync.aligned.m8n8.x4.trans.shared.b16 {%0,%1,%2,%3}, [%4];"
        : "=r"(r[0]), "=r"(r[1]), "=r"(r[2]), "=r"(r[3]) : "r"(a));
}

// ---------------------------------------------------------------------------
// Kernel 1: three 1x1 convs -> fp16 hi/lo operand buffers.
// 8 output channels per block (grid z=4) for occupancy.
// Q (conv0) natural [oc][hw] == q[n][c] flat; K (conv1) -> [m][c]; V (conv2)
// natural == v[m][c] flat.
// ---------------------------------------------------------------------------
__global__ __launch_bounds__(256) void qkv_kernel(
    const float* __restrict__ x,
    const float* __restrict__ w1, const float* __restrict__ b1,
    const float* __restrict__ w2, const float* __restrict__ b2,
    const float* __restrict__ w3, const float* __restrict__ b3)
{
    __shared__ float ws[8 * CIN];
    __shared__ float bsm[8];
    int conv = blockIdx.y;
    const float* w    = (conv == 0) ? w1 : (conv == 1) ? w2 : w3;
    const float* bias = (conv == 0) ? b1 : (conv == 1) ? b2 : b3;
    int ocb = blockIdx.z * 8;

    int t = threadIdx.x;
    for (int i = t; i < 8 * CIN; i += 256) ws[i] = w[ocb * CIN + i];
    if (t < 8) bsm[t] = bias[ocb + t];
    __syncthreads();

    int idx = blockIdx.x * 256 + t;
    int b = idx >> 12, hw = idx & 4095;
    const float* xp = x + b * (CIN * NFLAT) + hw;

    float acc[8];
#pragma unroll
    for (int oc = 0; oc < 8; oc++) acc[oc] = bsm[oc];
#pragma unroll 8
    for (int c = 0; c < CIN; c++) {
        float xv = xp[c * NFLAT];
#pragma unroll
        for (int oc = 0; oc < 8; oc++) acc[oc] += ws[oc * CIN + c] * xv;
    }

    if (conv != 1) {                    // Q or V: natural strided fp16
        __half* oh = (conv == 0 ? gQh : gVh) + b * BS + ocb * NFLAT + hw;
        __half* ol = (conv == 0 ? gQl : gVl) + b * BS + ocb * NFLAT + hw;
#pragma unroll
        for (int oc = 0; oc < 8; oc++) {
            float a = acc[oc];
            __half h = __float2half_rn(a);
            oh[oc * NFLAT] = h;
            ol[oc * NFLAT] = __float2half_rn(a - __half2float(h));
        }
    } else {                            // K: [m][c] contiguous 8 channels
        uint32_t hp[4], lp[4];
#pragma unroll
        for (int j = 0; j < 4; j++) {
            float a0 = acc[2*j], a1 = acc[2*j+1];
            __half h0 = __float2half_rn(a0), h1 = __float2half_rn(a1);
            float r0 = a0 - __half2float(h0);
            float r1 = a1 - __half2float(h1);
            __half l0 = __float2half_rn(r0), l1 = __float2half_rn(r1);
            hp[j] = ((uint32_t)__half_as_ushort(h1) << 16) | __half_as_ushort(h0);
            lp[j] = ((uint32_t)__half_as_ushort(l1) << 16) | __half_as_ushort(l0);
        }
        __half* kh = gKh + b * BS + hw * CH + ocb;
        __half* kl = gKl + b * BS + hw * CH + ocb;
        *(uint4*)kh = make_uint4(hp[0], hp[1], hp[2], hp[3]);
        *(uint4*)kl = make_uint4(lp[0], lp[1], lp[2], lp[3]);
    }
}

// ---------------------------------------------------------------------------
// Kernel 2: fused QK -> batch-softmax -> PV on mma.sync fp16.
// QK: 3-term split (hh+hl+lh).  PV: 2-term (Ph*Vh + Ph*Vl), P rounded once.
// CTA = 32 n rows x all 4 batches x full 4096 m (64 chunks of 64).
// Q fragments hoisted to registers for the whole mainloop (R13).
// 8 warps = 2 n-subtiles x 4 m-subtiles; softmax entirely in registers.
// Cross-wm partial-Y reduction via smem at the end.
// smem rows padded to 80B (ldmatrix conflict-free). cp.async double buffer.
// ---------------------------------------------------------------------------
#define QS  0
#define KSO 20480
#define VSO 102400
#define STG 40960
#define SMB 184320

__device__ __forceinline__ void stage_kv(uint32_t sb, int t, int m0, int stg)
{
#pragma unroll
    for (int i = 0; i < 8; i++) {
        int idx = t + 256 * i;
        int chk = idx & 3, row = (idx >> 2) & 63, hl = (idx >> 8) & 1, b = (idx >> 9) & 3;
        int goff = b * BS + (m0 + row) * CH + chk * 8;
        uint32_t soff = (uint32_t)((b * 2 + hl) * 5120 + row * 80 + chk * 16);
        const __half* kp = (hl ? gKl : gKh) + goff;
        const __half* vp = (hl ? gVl : gVh) + goff;
        uint32_t ka = sb + KSO + stg + soff;
        uint32_t va = sb + VSO + stg + soff;
        asm volatile("cp.async.cg.shared.global [%0], [%1], 16;" :: "r"(ka), "l"(kp) : "memory");
        asm volatile("cp.async.cg.shared.global [%0], [%1], 16;" :: "r"(va), "l"(vp) : "memory");
    }
    asm volatile("cp.async.commit_group;" ::: "memory");
}

__global__ __launch_bounds__(256, 1) void attn_kernel()
{
    extern __shared__ char smc[];
    uint32_t sb = smem_u32(smc);
    int t = threadIdx.x, w = t >> 5, l = t & 31;
    int g = l >> 2, tg = l & 3;
    int wn = w >> 2, wm = w & 3;
    int n0 = blockIdx.x * 32;

    // ---- stage Q tiles (once): [b][hl][32 rows][40 halves(pad)] ----
#pragma unroll
    for (int i = 0; i < 4; i++) {
        int idx = t + 256 * i;
        int chk = idx & 3, row = (idx >> 2) & 31, hl = (idx >> 7) & 1, b = (idx >> 8) & 3;
        const __half* src = (hl ? gQl : gQh) + b * BS + (n0 + row) * CH + chk * 8;
        *(uint4*)(smc + QS + (b * 2 + hl) * 2560 + row * 80 + chk * 16) =
            *(const uint4*)src;
    }

    // ldmatrix lane geometry (submatrix order == fragment reg order)
    int lr = l & 7, sub = l >> 3, subr = sub & 1, subc = sub >> 1;
    uint32_t rpq = (uint32_t)((wn * 16 + lr + subr * 8) * 80 + subc * 16);
    uint32_t rpk = (uint32_t)((wm * 16 + lr + subr * 8) * 80 + subc * 16);

    __syncthreads();                    // Q staged before hoisted ldsm

    // ---- Q fragments: loaded ONCE, live in registers all mainloop ----
    uint32_t qh[4][2][4], ql[4][2][4];
#pragma unroll
    for (int b = 0; b < 4; b++) {
        uint32_t qb = sb + QS + (b * 2) * 2560 + rpq;
        ldsm4(qh[b][0], qb);           ldsm4(qh[b][1], qb + 32);
        ldsm4(ql[b][0], qb + 2560);    ldsm4(ql[b][1], qb + 2560 + 32);
    }

    float Y[4][4][4];
#pragma unroll
    for (int b = 0; b < 4; b++)
#pragma unroll
        for (int cg = 0; cg < 4; cg++)
#pragma unroll
            for (int r = 0; r < 4; r++) Y[b][cg][r] = 0.0f;

    stage_kv(sb, t, 0, 0);              // prologue: chunk 0

    for (int c = 0; c < 64; c++) {
        asm volatile("cp.async.wait_group 0;" ::: "memory");
        __syncthreads();
        if (c < 63) stage_kv(sb, t, (c + 1) * 64, ((c + 1) & 1) * STG);
        uint32_t sbK = sb + KSO + (c & 1) * STG;
        uint32_t sbV = sb + VSO + (c & 1) * STG;

        // ---------------- QK: S_b = Q_b K_b^T (hh + hl + lh) ----------------
        float S[4][2][4];
#pragma unroll
        for (int b = 0; b < 4; b++) {
            uint32_t kh[2][4], kl[2][4];
            uint32_t kb = sbK + (b * 2) * 5120 + rpk;
            ldsm4(kh[0], kb);           ldsm4(kh[1], kb + 32);
            ldsm4(kl[0], kb + 5120);    ldsm4(kl[1], kb + 5120 + 32);
#pragma unroll
            for (int mg = 0; mg < 2; mg++)
#pragma unroll
                for (int r = 0; r < 4; r++) S[b][mg][r] = 0.0f;
#pragma unroll
            for (int kg = 0; kg < 2; kg++) {
                mma16816(S[b][0], qh[b][kg], kh[kg][0], kh[kg][2]);
                mma16816(S[b][1], qh[b][kg], kh[kg][1], kh[kg][3]);
                mma16816(S[b][0], qh[b][kg], kl[kg][0], kl[kg][2]);
                mma16816(S[b][1], qh[b][kg], kl[kg][1], kl[kg][3]);
                mma16816(S[b][0], ql[b][kg], kh[kg][0], kh[kg][2]);
                mma16816(S[b][1], ql[b][kg], kh[kg][1], kh[kg][3]);
            }
        }

        // ------- softmax over batch (pointwise), pack P once as fp16 -------
        uint32_t pH[4][4];
#pragma unroll
        for (int mg = 0; mg < 2; mg++)
#pragma unroll
            for (int rp = 0; rp < 2; rp++) {
                int a = mg * 2 + rp;
                float e0[4], e1[4], s0 = 0.f, s1 = 0.f;
#pragma unroll
                for (int b = 0; b < 4; b++) {
                    e0[b] = __expf(S[b][mg][rp * 2]);     s0 += e0[b];
                    e1[b] = __expf(S[b][mg][rp * 2 + 1]); s1 += e1[b];
                }
                float i0 = __fdividef(1.f, s0), i1 = __fdividef(1.f, s1);
#pragma unroll
                for (int b = 0; b < 4; b++)
                    pH[b][a] = pk_f16x2(e0[b] * i0, e1[b] * i1);
            }

        // ---------------- PV: Y_b += Ph_b (Vh_b + Vl_b) --------------------
#pragma unroll
        for (int b = 0; b < 4; b++) {
            uint32_t vh[2][4], vl[2][4];
            uint32_t vb = sbV + (b * 2) * 5120 + rpk;
            ldsm4t(vh[0], vb);          ldsm4t(vh[1], vb + 32);
            ldsm4t(vl[0], vb + 5120);   ldsm4t(vl[1], vb + 5120 + 32);
#pragma unroll
            for (int cg = 0; cg < 4; cg++) {
                uint32_t bh0 = vh[cg >> 1][(cg & 1) * 2];
                uint32_t bh1 = vh[cg >> 1][(cg & 1) * 2 + 1];
                uint32_t bl0 = vl[cg >> 1][(cg & 1) * 2];
                uint32_t bl1 = vl[cg >> 1][(cg & 1) * 2 + 1];
                mma16816(Y[b][cg], pH[b], bh0, bh1);
                mma16816(Y[b][cg], pH[b], bl0, bl1);
            }
        }
    }

    // ---- cross-wm reduction of partial Y, then write ----
    __syncthreads();                    // all warps done reading K/V smem
    float* red = (float*)smc;           // 8w x 64e x 32 lanes = 64 KB
#pragma unroll
    for (int b = 0; b < 4; b++)
#pragma unroll
        for (int cg = 0; cg < 4; cg++)
#pragma unroll
            for (int r = 0; r < 4; r++)
                red[(w * 64 + b * 16 + cg * 4 + r) * 32 + l] = Y[b][cg][r];
    __syncthreads();
    {
        int b = wm;                     // warp (wn,wm) reduces batch wm
        float o[16];
#pragma unroll
        for (int cg = 0; cg < 4; cg++)
#pragma unroll
            for (int r = 0; r < 4; r++) {
                int e = b * 16 + cg * 4 + r;
                o[cg * 4 + r] =
                      red[((wn * 4 + 0) * 64 + e) * 32 + l]
                    + red[((wn * 4 + 1) * 64 + e) * 32 + l]
                    + red[((wn * 4 + 2) * 64 + e) * 32 + l]
                    + red[((wn * 4 + 3) * 64 + e) * 32 + l];
            }
        int n = n0 + wn * 16 + g;
#pragma unroll
        for (int cg = 0; cg < 4; cg++) {
            int cc = cg * 8 + tg * 2;
            *(float2*)(gY + b * BS + n * CH + cc) =
                make_float2(o[cg * 4 + 0], o[cg * 4 + 1]);
            *(float2*)(gY + b * BS + (n + 8) * CH + cc) =
                make_float2(o[cg * 4 + 2], o[cg * 4 + 3]);
        }
    }
}

// ---------------------------------------------------------------------------
// Kernel 3: final 1x1 conv (32->64). 16 co per block (grid y=4) for occupancy.
// gY flat == y2[b][ci][hw].
// ---------------------------------------------------------------------------
__global__ __launch_bounds__(256) void outconv_kernel(
    const float* __restrict__ w4, const float* __restrict__ b4,
    float* __restrict__ out)
{
    __shared__ float ws[16 * CH];
    __shared__ float bsm[16];
    int t = threadIdx.x;
    int cob = blockIdx.y * 16;
    for (int i = t; i < 16 * CH; i += 256) ws[i] = w4[cob * CH + i];
    if (t < 16) bsm[t] = b4[cob + t];
    __syncthreads();

    int idx = blockIdx.x * 256 + t;
    int b = idx >> 12, hw = idx & 4095;
    const float* yp = gY + b * BS + hw;

    float acc[16];
#pragma unroll
    for (int co = 0; co < 16; co++) acc[co] = bsm[co];

#pragma unroll 8
    for (int ci = 0; ci < CH; ci++) {
        float yv = yp[ci * NFLAT];
#pragma unroll
        for (int co = 0; co < 16; co++) acc[co] += ws[co * CH + ci] * yv;
    }

    float* op = out + b * (CIN * NFLAT) + cob * NFLAT + hw;
#pragma unroll
    for (int co = 0; co < 16; co++) op[co * NFLAT] = acc[co];
}

// ---------------------------------------------------------------------------
extern "C" void kernel_launch(void* const* d_in, const int* in_sizes, int n_in,
                              void* d_out, int out_size)
{
    const float* x  = (const float*)d_in[0];
    const float* w1 = (const float*)d_in[1];
    const float* b1 = (const float*)d_in[2];
    const float* w2 = (const float*)d_in[3];
    const float* b2 = (const float*)d_in[4];
    const float* w3 = (const float*)d_in[5];
    const float* b3 = (const float*)d_in[6];
    const float* w4 = (const float*)d_in[7];
    const float* b4 = (const float*)d_in[8];
    float* out = (float*)d_out;

    cudaFuncSetAttribute(attn_kernel,
                         cudaFuncAttributeMaxDynamicSharedMemorySize, SMB);

    qkv_kernel<<<dim3(64, 3, 4), 256>>>(x, w1, b1, w2, b2, w3, b3);
    attn_kernel<<<128, 256, SMB>>>();
    outconv_kernel<<<dim3(64, 4), 256>>>(w4, b4, out);
}

// round 14
// speedup vs baseline: 3.5141x; 1.0107x over previous
#include <cuda_runtime.h>
#include <cuda_fp16.h>
#include <cstdint>

#define NFLAT 4096
#define CH    32
#define CIN   64
#define BS    (CH * NFLAT)            // 131072 elems per batch

// Scratch (allocation-free rule: __device__ globals)
__device__ __half gQh[4 * BS], gQl[4 * BS];  // flat == q[b][n*32+c]
__device__ __half gKh[4 * BS], gKl[4 * BS];  // [b][m][c]
__device__ __half gVh[4 * BS], gVl[4 * BS];  // flat == v[b][m*32+c]
__device__ float gY[4 * BS];                 // [b][n][c] == y2[b][ci][hw]

// ---------------------------------------------------------------------------
// helpers
// ---------------------------------------------------------------------------
__device__ __forceinline__ uint32_t smem_u32(const void* p) {
    uint32_t a;
    asm("{ .reg .u64 t; cvta.to.shared.u64 t, %1; cvt.u32.u64 %0, t; }"
        : "=r"(a) : "l"(p));
    return a;
}
// pack 2 floats -> f16x2 (first arg -> low half)
__device__ __forceinline__ uint32_t pk_f16x2(float lo, float hi) {
    uint32_t r;
    asm("cvt.rn.f16x2.f32 %0, %1, %2;" : "=r"(r) : "f"(hi), "f"(lo));
    return r;
}
__device__ __forceinline__ void mma16816(float* d, const uint32_t* a,
                                         uint32_t b0, uint32_t b1) {
    asm volatile(
        "mma.sync.aligned.m16n8k16.row.col.f32.f16.f16.f32 "
        "{%0,%1,%2,%3}, {%4,%5,%6,%7}, {%8,%9}, {%0,%1,%2,%3};"
        : "+f"(d[0]), "+f"(d[1]), "+f"(d[2]), "+f"(d[3])
        : "r"(a[0]), "r"(a[1]), "r"(a[2]), "r"(a[3]), "r"(b0), "r"(b1));
}
__device__ __forceinline__ void ldsm4(uint32_t* r, uint32_t a) {
    asm volatile("ldmatrix.sync.aligned.m8n8.x4.shared.b16 {%0,%1,%2,%3}, [%4];"
        : "=r"(r[0]), "=r"(r[1]), "=r"(r[2]), "=r"(r[3]) : "r"(a));
}
__device__ __forceinline__ void ldsm4t(uint32_t* r, uint32_t a) {
    asm volatile("ldmatrix.sync.aligned.m8n8.x4.trans.shared.b16 {%0,%1,%2,%3}, [%4];"
        : "=r"(r[0]), "=r"(r[1]), "=r"(r[2]), "=r"(r[3]) : "r"(a));
}

// ---------------------------------------------------------------------------
// Kernel 1: three 1x1 convs -> fp16 hi/lo operand buffers. (as R13)
// ---------------------------------------------------------------------------
__global__ __launch_bounds__(256) void qkv_kernel(
    const float* __restrict__ x,
    const float* __restrict__ w1, const float* __restrict__ b1,
    const float* __restrict__ w2, const float* __restrict__ b2,
    const float* __restrict__ w3, const float* __restrict__ b3)
{
    __shared__ float ws[8 * CIN];
    __shared__ float bsm[8];
    int conv = blockIdx.y;
    const float* w    = (conv == 0) ? w1 : (conv == 1) ? w2 : w3;
    const float* bias = (conv == 0) ? b1 : (conv == 1) ? b2 : b3;
    int ocb = blockIdx.z * 8;

    int t = threadIdx.x;
    for (int i = t; i < 8 * CIN; i += 256) ws[i] = w[ocb * CIN + i];
    if (t < 8) bsm[t] = bias[ocb + t];
    __syncthreads();

    int idx = blockIdx.x * 256 + t;
    int b = idx >> 12, hw = idx & 4095;
    const float* xp = x + b * (CIN * NFLAT) + hw;

    float acc[8];
#pragma unroll
    for (int oc = 0; oc < 8; oc++) acc[oc] = bsm[oc];
#pragma unroll 8
    for (int c = 0; c < CIN; c++) {
        float xv = xp[c * NFLAT];
#pragma unroll
        for (int oc = 0; oc < 8; oc++) acc[oc] += ws[oc * CIN + c] * xv;
    }

    if (conv != 1) {                    // Q or V: natural strided fp16
        __half* oh = (conv == 0 ? gQh : gVh) + b * BS + ocb * NFLAT + hw;
        __half* ol = (conv == 0 ? gQl : gVl) + b * BS + ocb * NFLAT + hw;
#pragma unroll
        for (int oc = 0; oc < 8; oc++) {
            float a = acc[oc];
            __half h = __float2half_rn(a);
            oh[oc * NFLAT] = h;
            ol[oc * NFLAT] = __float2half_rn(a - __half2float(h));
        }
    } else {                            // K: [m][c] contiguous 8 channels
        uint32_t hp[4], lp[4];
#pragma unroll
        for (int j = 0; j < 4; j++) {
            float a0 = acc[2*j], a1 = acc[2*j+1];
            __half h0 = __float2half_rn(a0), h1 = __float2half_rn(a1);
            float r0 = a0 - __half2float(h0);
            float r1 = a1 - __half2float(h1);
            __half l0 = __float2half_rn(r0), l1 = __float2half_rn(r1);
            hp[j] = ((uint32_t)__half_as_ushort(h1) << 16) | __half_as_ushort(h0);
            lp[j] = ((uint32_t)__half_as_ushort(l1) << 16) | __half_as_ushort(l0);
        }
        __half* kh = gKh + b * BS + hw * CH + ocb;
        __half* kl = gKl + b * BS + hw * CH + ocb;
        *(uint4*)kh = make_uint4(hp[0], hp[1], hp[2], hp[3]);
        *(uint4*)kl = make_uint4(lp[0], lp[1], lp[2], lp[3]);
    }
}

// ---------------------------------------------------------------------------
// Kernel 2: fused QK -> batch-softmax -> PV, fp16 mma.sync.
// R14: 512 threads, 16 warps = (wn 0..1, wm 0..3, half 0..1).
// Each warp owns 2 batches (half*2, half*2+1) for its 16n x 16m tile; the
// warp pair exchanges exp(S) via smem + named barrier so the 4-batch softmax
// stays correct while per-warp registers halve (4 warps/SMSP now).
// ---------------------------------------------------------------------------
#define QS  0
#define KSO 20480
#define VSO 102400
#define STG 40960
#define EXO 184320
#define SMB 217088

__device__ __forceinline__ void stage_kv(uint32_t sb, int t, int m0, int stg)
{
#pragma unroll
    for (int i = 0; i < 4; i++) {
        int idx = t + 512 * i;
        int chk = idx & 3, row = (idx >> 2) & 63, hl = (idx >> 8) & 1, b = (idx >> 9) & 3;
        int goff = b * BS + (m0 + row) * CH + chk * 8;
        uint32_t soff = (uint32_t)((b * 2 + hl) * 5120 + row * 80 + chk * 16);
        const __half* kp = (hl ? gKl : gKh) + goff;
        const __half* vp = (hl ? gVl : gVh) + goff;
        uint32_t ka = sb + KSO + stg + soff;
        uint32_t va = sb + VSO + stg + soff;
        asm volatile("cp.async.cg.shared.global [%0], [%1], 16;" :: "r"(ka), "l"(kp) : "memory");
        asm volatile("cp.async.cg.shared.global [%0], [%1], 16;" :: "r"(va), "l"(vp) : "memory");
    }
    asm volatile("cp.async.commit_group;" ::: "memory");
}

__global__ __launch_bounds__(512, 1) void attn_kernel()
{
    extern __shared__ char smc[];
    uint32_t sb = smem_u32(smc);
    int t = threadIdx.x, w = t >> 5, l = t & 31;
    int g = l >> 2, tg = l & 3;
    int wn = w >> 3, wm = (w >> 1) & 3, half = w & 1;
    int pair = w >> 1;                  // 0..7; named barrier id = pair+1
    int n0 = blockIdx.x * 32;
    float* ex = (float*)(smc + EXO);    // [pair][b][mg][r][lane]

    // ---- stage Q tiles (once): [b][hl][32 rows][40 halves(pad)] ----
#pragma unroll
    for (int i = 0; i < 2; i++) {
        int idx = t + 512 * i;
        int chk = idx & 3, row = (idx >> 2) & 31, hl = (idx >> 7) & 1, b = (idx >> 8) & 3;
        const __half* src = (hl ? gQl : gQh) + b * BS + (n0 + row) * CH + chk * 8;
        *(uint4*)(smc + QS + (b * 2 + hl) * 2560 + row * 80 + chk * 16) =
            *(const uint4*)src;
    }

    // ldmatrix lane geometry
    int lr = l & 7, sub = l >> 3, subr = sub & 1, subc = sub >> 1;
    uint32_t rpq = (uint32_t)((wn * 16 + lr + subr * 8) * 80 + subc * 16);
    uint32_t rpk = (uint32_t)((wm * 16 + lr + subr * 8) * 80 + subc * 16);

    __syncthreads();                    // Q staged before hoisted ldsm

    // ---- Q fragments for this warp's 2 batches: live all mainloop ----
    uint32_t qh[2][2][4], ql[2][2][4];
#pragma unroll
    for (int ob = 0; ob < 2; ob++) {
        int b = half * 2 + ob;
        uint32_t qb = sb + QS + (b * 2) * 2560 + rpq;
        ldsm4(qh[ob][0], qb);           ldsm4(qh[ob][1], qb + 32);
        ldsm4(ql[ob][0], qb + 2560);    ldsm4(ql[ob][1], qb + 2560 + 32);
    }

    float Y[2][4][4];
#pragma unroll
    for (int ob = 0; ob < 2; ob++)
#pragma unroll
        for (int cg = 0; cg < 4; cg++)
#pragma unroll
            for (int r = 0; r < 4; r++) Y[ob][cg][r] = 0.0f;

    stage_kv(sb, t, 0, 0);              // prologue: chunk 0

    for (int c = 0; c < 64; c++) {
        asm volatile("cp.async.wait_group 0;" ::: "memory");
        __syncthreads();
        if (c < 63) stage_kv(sb, t, (c + 1) * 64, ((c + 1) & 1) * STG);
        uint32_t sbK = sb + KSO + (c & 1) * STG;
        uint32_t sbV = sb + VSO + (c & 1) * STG;

        // ------------- QK for own 2 batches (hh + hl + lh) -------------
        float e[2][2][4];               // exp(S) for own batches
#pragma unroll
        for (int ob = 0; ob < 2; ob++) {
            int b = half * 2 + ob;
            uint32_t kh[2][4], kl[2][4];
            uint32_t kb = sbK + (b * 2) * 5120 + rpk;
            ldsm4(kh[0], kb);           ldsm4(kh[1], kb + 32);
            ldsm4(kl[0], kb + 5120);    ldsm4(kl[1], kb + 5120 + 32);
            float S[2][4];
#pragma unroll
            for (int mg = 0; mg < 2; mg++)
#pragma unroll
                for (int r = 0; r < 4; r++) S[mg][r] = 0.0f;
#pragma unroll
            for (int kg = 0; kg < 2; kg++) {
                mma16816(S[0], qh[ob][kg], kh[kg][0], kh[kg][2]);
                mma16816(S[1], qh[ob][kg], kh[kg][1], kh[kg][3]);
                mma16816(S[0], qh[ob][kg], kl[kg][0], kl[kg][2]);
                mma16816(S[1], qh[ob][kg], kl[kg][1], kl[kg][3]);
                mma16816(S[0], ql[ob][kg], kh[kg][0], kh[kg][2]);
                mma16816(S[1], ql[ob][kg], kh[kg][1], kh[kg][3]);
            }
#pragma unroll
            for (int mg = 0; mg < 2; mg++)
#pragma unroll
                for (int r = 0; r < 4; r++) e[ob][mg][r] = __expf(S[mg][r]);
        }

        // ------------- exchange exp(S) within warp pair -------------
#pragma unroll
        for (int ob = 0; ob < 2; ob++) {
            int b = half * 2 + ob;
#pragma unroll
            for (int mg = 0; mg < 2; mg++)
#pragma unroll
                for (int r = 0; r < 4; r++)
                    ex[((pair * 4 + b) * 8 + mg * 4 + r) * 32 + l] = e[ob][mg][r];
        }
        asm volatile("bar.sync %0, %1;" :: "r"(pair + 1), "r"(64) : "memory");
        float eo[2][2][4];              // other half's batches
#pragma unroll
        for (int ob = 0; ob < 2; ob++) {
            int b = (1 - half) * 2 + ob;
#pragma unroll
            for (int mg = 0; mg < 2; mg++)
#pragma unroll
                for (int r = 0; r < 4; r++)
                    eo[ob][mg][r] = ex[((pair * 4 + b) * 8 + mg * 4 + r) * 32 + l];
        }

        // ------------- softmax over batch; pack P once as fp16 -------------
        uint32_t pH[2][4];
#pragma unroll
        for (int mg = 0; mg < 2; mg++)
#pragma unroll
            for (int rp = 0; rp < 2; rp++) {
                int a = mg * 2 + rp;
                float s0 = e[0][mg][rp*2]   + e[1][mg][rp*2]
                         + eo[0][mg][rp*2]  + eo[1][mg][rp*2];
                float s1 = e[0][mg][rp*2+1] + e[1][mg][rp*2+1]
                         + eo[0][mg][rp*2+1] + eo[1][mg][rp*2+1];
                float i0 = __fdividef(1.f, s0), i1 = __fdividef(1.f, s1);
#pragma unroll
                for (int ob = 0; ob < 2; ob++)
                    pH[ob][a] = pk_f16x2(e[ob][mg][rp*2] * i0,
                                         e[ob][mg][rp*2+1] * i1);
            }

        // ------------- PV: Y_ob += Ph_ob (Vh_b + Vl_b) -------------
#pragma unroll
        for (int ob = 0; ob < 2; ob++) {
            int b = half * 2 + ob;
            uint32_t vh[2][4], vl[2][4];
            uint32_t vb = sbV + (b * 2) * 5120 + rpk;
            ldsm4t(vh[0], vb);          ldsm4t(vh[1], vb + 32);
            ldsm4t(vl[0], vb + 5120);   ldsm4t(vl[1], vb + 5120 + 32);
#pragma unroll
            for (int cg = 0; cg < 4; cg++) {
                uint32_t bh0 = vh[cg >> 1][(cg & 1) * 2];
                uint32_t bh1 = vh[cg >> 1][(cg & 1) * 2 + 1];
                uint32_t bl0 = vl[cg >> 1][(cg & 1) * 2];
                uint32_t bl1 = vl[cg >> 1][(cg & 1) * 2 + 1];
                mma16816(Y[ob][cg], pH[ob], bh0, bh1);
                mma16816(Y[ob][cg], pH[ob], bl0, bl1);
            }
        }
    }

    // ---- cross-wm reduction of partial Y, then write ----
    __syncthreads();                    // all warps done with K/V smem
    float* red = (float*)smc;           // 16w x 32e x 32 lanes = 64 KB
#pragma unroll
    for (int ob = 0; ob < 2; ob++)
#pragma unroll
        for (int cg = 0; cg < 4; cg++)
#pragma unroll
            for (int r = 0; r < 4; r++)
                red[(w * 32 + ob * 16 + cg * 4 + r) * 32 + l] = Y[ob][cg][r];
    __syncthreads();
    {
        // task: warp w reduces (wn_r, batch rb, cg-half cgh) over wm 0..3
        int wn_r = w >> 3, rb = (w >> 1) & 3, cgh = w & 1;
        int sh = rb >> 1, sob = rb & 1;  // source half, source ob slot
        float o[2][4];
#pragma unroll
        for (int cgi = 0; cgi < 2; cgi++) {
            int cg = cgh * 2 + cgi;
#pragma unroll
            for (int r = 0; r < 4; r++) {
                int e2 = sob * 16 + cg * 4 + r;
                o[cgi][r] =
                      red[((wn_r * 8 + 0 * 2 + sh) * 32 + e2) * 32 + l]
                    + red[((wn_r * 8 + 1 * 2 + sh) * 32 + e2) * 32 + l]
                    + red[((wn_r * 8 + 2 * 2 + sh) * 32 + e2) * 32 + l]
                    + red[((wn_r * 8 + 3 * 2 + sh) * 32 + e2) * 32 + l];
            }
        }
        int n = n0 + wn_r * 16 + g;
#pragma unroll
        for (int cgi = 0; cgi < 2; cgi++) {
            int cg = cgh * 2 + cgi;
            int cc = cg * 8 + tg * 2;
            *(float2*)(gY + rb * BS + n * CH + cc) =
                make_float2(o[cgi][0], o[cgi][1]);
            *(float2*)(gY + rb * BS + (n + 8) * CH + cc) =
                make_float2(o[cgi][2], o[cgi][3]);
        }
    }
}

// ---------------------------------------------------------------------------
// Kernel 3: final 1x1 conv (32->64). 16 co per block. (as R13)
// ---------------------------------------------------------------------------
__global__ __launch_bounds__(256) void outconv_kernel(
    const float* __restrict__ w4, const float* __restrict__ b4,
    float* __restrict__ out)
{
    __shared__ float ws[16 * CH];
    __shared__ float bsm[16];
    int t = threadIdx.x;
    int cob = blockIdx.y * 16;
    for (int i = t; i < 16 * CH; i += 256) ws[i] = w4[cob * CH + i];
    if (t < 16) bsm[t] = b4[cob + t];
    __syncthreads();

    int idx = blockIdx.x * 256 + t;
    int b = idx >> 12, hw = idx & 4095;
    const float* yp = gY + b * BS + hw;

    float acc[16];
#pragma unroll
    for (int co = 0; co < 16; co++) acc[co] = bsm[co];

#pragma unroll 8
    for (int ci = 0; ci < CH; ci++) {
        float yv = yp[ci * NFLAT];
#pragma unroll
        for (int co = 0; co < 16; co++) acc[co] += ws[co * CH + ci] * yv;
    }

    float* op = out + b * (CIN * NFLAT) + cob * NFLAT + hw;
#pragma unroll
    for (int co = 0; co < 16; co++) op[co * NFLAT] = acc[co];
}

// ---------------------------------------------------------------------------
extern "C" void kernel_launch(void* const* d_in, const int* in_sizes, int n_in,
                              void* d_out, int out_size)
{
    const float* x  = (const float*)d_in[0];
    const float* w1 = (const float*)d_in[1];
    const float* b1 = (const float*)d_in[2];
    const float* w2 = (const float*)d_in[3];
    const float* b2 = (const float*)d_in[4];
    const float* w3 = (const float*)d_in[5];
    const float* b3 = (const float*)d_in[6];
    const float* w4 = (const float*)d_in[7];
    const float* b4 = (const float*)d_in[8];
    float* out = (float*)d_out;

    cudaFuncSetAttribute(attn_kernel,
                         cudaFuncAttributeMaxDynamicSharedMemorySize, SMB);

    qkv_kernel<<<dim3(64, 3, 4), 256>>>(x, w1, b1, w2, b2, w3, b3);
    attn_kernel<<<128, 512, SMB>>>();
    outconv_kernel<<<dim3(64, 4), 256>>>(w4, b4, out);
}

// round 17
// speedup vs baseline: 4.0454x; 1.1512x over previous
#include <cuda_runtime.h>
#include <cuda_fp16.h>
#include <cstdint>

#define NFLAT 4096
#define CH    32
#define CIN   64
#define BS    (CH * NFLAT)            // 131072 elems per batch

// Scratch (allocation-free rule: __device__ globals)
__device__ __half gQh[4 * BS], gQl[4 * BS];  // flat == q[b][n*32+c]
__device__ __half gKh[4 * BS], gKl[4 * BS];  // [b][m][c]
__device__ __half gVh[4 * BS];               // flat == v[b][m*32+c]
__device__ float gY[4 * BS];                 // [b][n][c] == y2[b][ci][hw]

// ---------------------------------------------------------------------------
// helpers
// ---------------------------------------------------------------------------
__device__ __forceinline__ uint32_t smem_u32(const void* p) {
    uint32_t a;
    asm("{ .reg .u64 t; cvta.to.shared.u64 t, %1; cvt.u32.u64 %0, t; }"
        : "=r"(a) : "l"(p));
    return a;
}
// pack 2 floats -> f16x2 (first arg -> low half)
__device__ __forceinline__ uint32_t pk_f16x2(float lo, float hi) {
    uint32_t r;
    asm("cvt.rn.f16x2.f32 %0, %1, %2;" : "=r"(r) : "f"(hi), "f"(lo));
    return r;
}
__device__ __forceinline__ void mma16816(float* d, const uint32_t* a,
                                         uint32_t b0, uint32_t b1) {
    asm volatile(
        "mma.sync.aligned.m16n8k16.row.col.f32.f16.f16.f32 "
        "{%0,%1,%2,%3}, {%4,%5,%6,%7}, {%8,%9}, {%0,%1,%2,%3};"
        : "+f"(d[0]), "+f"(d[1]), "+f"(d[2]), "+f"(d[3])
        : "r"(a[0]), "r"(a[1]), "r"(a[2]), "r"(a[3]), "r"(b0), "r"(b1));
}
__device__ __forceinline__ void ldsm4(uint32_t* r, uint32_t a) {
    asm volatile("ldmatrix.sync.aligned.m8n8.x4.shared.b16 {%0,%1,%2,%3}, [%4];"
        : "=r"(r[0]), "=r"(r[1]), "=r"(r[2]), "=r"(r[3]) : "r"(a));
}
__device__ __forceinline__ void ldsm4t(uint32_t* r, uint32_t a) {
    asm volatile("ldmatrix.sync.aligned.m8n8.x4.trans.shared.b16 {%0,%1,%2,%3}, [%4];"
        : "=r"(r[0]), "=r"(r[1]), "=r"(r[2]), "=r"(r[3]) : "r"(a));
}

// ---------------------------------------------------------------------------
// Kernel 1: three 1x1 convs -> fp16 operand buffers.
// Q hi/lo, K hi/lo, V hi only (PV is single-term).
// ---------------------------------------------------------------------------
__global__ __launch_bounds__(256) void qkv_kernel(
    const float* __restrict__ x,
    const float* __restrict__ w1, const float* __restrict__ b1,
    const float* __restrict__ w2, const float* __restrict__ b2,
    const float* __restrict__ w3, const float* __restrict__ b3)
{
    __shared__ float ws[8 * CIN];
    __shared__ float bsm[8];
    int conv = blockIdx.y;
    const float* w    = (conv == 0) ? w1 : (conv == 1) ? w2 : w3;
    const float* bias = (conv == 0) ? b1 : (conv == 1) ? b2 : b3;
    int ocb = blockIdx.z * 8;

    int t = threadIdx.x;
    for (int i = t; i < 8 * CIN; i += 256) ws[i] = w[ocb * CIN + i];
    if (t < 8) bsm[t] = bias[ocb + t];
    __syncthreads();

    int idx = blockIdx.x * 256 + t;
    int b = idx >> 12, hw = idx & 4095;
    const float* xp = x + b * (CIN * NFLAT) + hw;

    float acc[8];
#pragma unroll
    for (int oc = 0; oc < 8; oc++) acc[oc] = bsm[oc];
#pragma unroll 8
    for (int c = 0; c < CIN; c++) {
        float xv = xp[c * NFLAT];
#pragma unroll
        for (int oc = 0; oc < 8; oc++) acc[oc] += ws[oc * CIN + c] * xv;
    }

    if (conv == 0) {                    // Q: hi/lo, natural strided
        __half* oh = gQh + b * BS + ocb * NFLAT + hw;
        __half* ol = gQl + b * BS + ocb * NFLAT + hw;
#pragma unroll
        for (int oc = 0; oc < 8; oc++) {
            float a = acc[oc];
            __half h = __float2half_rn(a);
            oh[oc * NFLAT] = h;
            ol[oc * NFLAT] = __float2half_rn(a - __half2float(h));
        }
    } else if (conv == 2) {             // V: hi only, natural strided
        __half* oh = gVh + b * BS + ocb * NFLAT + hw;
#pragma unroll
        for (int oc = 0; oc < 8; oc++) oh[oc * NFLAT] = __float2half_rn(acc[oc]);
    } else {                            // K: [m][c] contiguous 8 channels
        uint32_t hp[4], lp[4];
#pragma unroll
        for (int j = 0; j < 4; j++) {
            float a0 = acc[2*j], a1 = acc[2*j+1];
            __half h0 = __float2half_rn(a0), h1 = __float2half_rn(a1);
            float r0 = a0 - __half2float(h0);
            float r1 = a1 - __half2float(h1);
            __half l0 = __float2half_rn(r0), l1 = __float2half_rn(r1);
            hp[j] = ((uint32_t)__half_as_ushort(h1) << 16) | __half_as_ushort(h0);
            lp[j] = ((uint32_t)__half_as_ushort(l1) << 16) | __half_as_ushort(l0);
        }
        __half* kh = gKh + b * BS + hw * CH + ocb;
        __half* kl = gKl + b * BS + hw * CH + ocb;
        *(uint4*)kh = make_uint4(hp[0], hp[1], hp[2], hp[3]);
        *(uint4*)kl = make_uint4(lp[0], lp[1], lp[2], lp[3]);
    }
}

// ---------------------------------------------------------------------------
// Kernel 2: fused QK -> batch-softmax -> PV, fp16 mma.sync.
// R17: structure = R14 (grid 128 n-tiles, full 4096-m walk, single gY);
// numerics = QK 3-term (hh+hl+lh), PV SINGLE term (Ph*Vh).
// 512 threads, 16 warps = (wn, wm, half); each warp owns 2 batches; warp
// pair exchanges exp(S) via smem + named barrier for the 4-batch softmax.
// ---------------------------------------------------------------------------
#define QS   0
#define KSO  20480
#define KSTG 40960
#define VSO  102400
#define VSTG 20480
#define EXO  143360
#define SMB  176128

__device__ __forceinline__ void stage_kv(uint32_t sb, int t, int m0, int stg)
{
    // K: hi+lo, 4 batches (2048 x 16B)
#pragma unroll
    for (int i = 0; i < 4; i++) {
        int idx = t + 512 * i;
        int chk = idx & 3, row = (idx >> 2) & 63, hl = (idx >> 8) & 1, b = (idx >> 9) & 3;
        const __half* kp = (hl ? gKl : gKh) + b * BS + (m0 + row) * CH + chk * 8;
        uint32_t ka = sb + KSO + stg * KSTG
                    + (uint32_t)((b * 2 + hl) * 5120 + row * 80 + chk * 16);
        asm volatile("cp.async.cg.shared.global [%0], [%1], 16;" :: "r"(ka), "l"(kp) : "memory");
    }
    // V: hi only, 4 batches (1024 x 16B)
#pragma unroll
    for (int i = 0; i < 2; i++) {
        int idx = t + 512 * i;
        int chk = idx & 3, row = (idx >> 2) & 63, b = (idx >> 8) & 3;
        const __half* vp = gVh + b * BS + (m0 + row) * CH + chk * 8;
        uint32_t va = sb + VSO + stg * VSTG
                    + (uint32_t)(b * 5120 + row * 80 + chk * 16);
        asm volatile("cp.async.cg.shared.global [%0], [%1], 16;" :: "r"(va), "l"(vp) : "memory");
    }
    asm volatile("cp.async.commit_group;" ::: "memory");
}

__global__ __launch_bounds__(512, 1) void attn_kernel()
{
    extern __shared__ char smc[];
    uint32_t sb = smem_u32(smc);
    int t = threadIdx.x, w = t >> 5, l = t & 31;
    int g = l >> 2, tg = l & 3;
    int wn = w >> 3, wm = (w >> 1) & 3, half = w & 1;
    int pair = w >> 1;                  // 0..7; named barrier id = pair+1
    int n0 = blockIdx.x * 32;
    float* ex = (float*)(smc + EXO);    // [pair][b][mg][r][lane]

    // ---- stage Q tiles (once): [b][hl][32 rows][40 halves(pad)] ----
#pragma unroll
    for (int i = 0; i < 2; i++) {
        int idx = t + 512 * i;
        int chk = idx & 3, row = (idx >> 2) & 31, hl = (idx >> 7) & 1, b = (idx >> 8) & 3;
        const __half* src = (hl ? gQl : gQh) + b * BS + (n0 + row) * CH + chk * 8;
        *(uint4*)(smc + QS + (b * 2 + hl) * 2560 + row * 80 + chk * 16) =
            *(const uint4*)src;
    }

    // ldmatrix lane geometry
    int lr = l & 7, sub = l >> 3, subr = sub & 1, subc = sub >> 1;
    uint32_t rpq = (uint32_t)((wn * 16 + lr + subr * 8) * 80 + subc * 16);
    uint32_t rpk = (uint32_t)((wm * 16 + lr + subr * 8) * 80 + subc * 16);

    __syncthreads();                    // Q staged before hoisted ldsm

    // ---- Q fragments for this warp's 2 batches: live all mainloop ----
    uint32_t qh[2][2][4], ql[2][2][4];
#pragma unroll
    for (int ob = 0; ob < 2; ob++) {
        int b = half * 2 + ob;
        uint32_t qb = sb + QS + (b * 2) * 2560 + rpq;
        ldsm4(qh[ob][0], qb);           ldsm4(qh[ob][1], qb + 32);
        ldsm4(ql[ob][0], qb + 2560);    ldsm4(ql[ob][1], qb + 2560 + 32);
    }

    float Y[2][4][4];
#pragma unroll
    for (int ob = 0; ob < 2; ob++)
#pragma unroll
        for (int cg = 0; cg < 4; cg++)
#pragma unroll
            for (int r = 0; r < 4; r++) Y[ob][cg][r] = 0.0f;

    stage_kv(sb, t, 0, 0);              // prologue: chunk 0

    for (int c = 0; c < 64; c++) {
        asm volatile("cp.async.wait_group 0;" ::: "memory");
        __syncthreads();
        if (c < 63) stage_kv(sb, t, (c + 1) * 64, (c + 1) & 1);
        uint32_t sbK = sb + KSO + (c & 1) * KSTG;
        uint32_t sbV = sb + VSO + (c & 1) * VSTG;

        // ------------- QK for own 2 batches (hh + hl + lh) -------------
        float e[2][2][4];               // exp(S) for own batches
#pragma unroll
        for (int ob = 0; ob < 2; ob++) {
            int b = half * 2 + ob;
            uint32_t kh[2][4], kl[2][4];
            uint32_t kb = sbK + (b * 2) * 5120 + rpk;
            ldsm4(kh[0], kb);           ldsm4(kh[1], kb + 32);
            ldsm4(kl[0], kb + 5120);    ldsm4(kl[1], kb + 5120 + 32);
            float S[2][4];
#pragma unroll
            for (int mg = 0; mg < 2; mg++)
#pragma unroll
                for (int r = 0; r < 4; r++) S[mg][r] = 0.0f;
#pragma unroll
            for (int kg = 0; kg < 2; kg++) {
                mma16816(S[0], qh[ob][kg], kh[kg][0], kh[kg][2]);
                mma16816(S[1], qh[ob][kg], kh[kg][1], kh[kg][3]);
                mma16816(S[0], qh[ob][kg], kl[kg][0], kl[kg][2]);
                mma16816(S[1], qh[ob][kg], kl[kg][1], kl[kg][3]);
                mma16816(S[0], ql[ob][kg], kh[kg][0], kh[kg][2]);
                mma16816(S[1], ql[ob][kg], kh[kg][1], kh[kg][3]);
            }
#pragma unroll
            for (int mg = 0; mg < 2; mg++)
#pragma unroll
                for (int r = 0; r < 4; r++) e[ob][mg][r] = __expf(S[mg][r]);
        }

        // ------------- exchange exp(S) within warp pair -------------
#pragma unroll
        for (int ob = 0; ob < 2; ob++) {
            int b = half * 2 + ob;
#pragma unroll
            for (int mg = 0; mg < 2; mg++)
#pragma unroll
                for (int r = 0; r < 4; r++)
                    ex[((pair * 4 + b) * 8 + mg * 4 + r) * 32 + l] = e[ob][mg][r];
        }
        asm volatile("bar.sync %0, %1;" :: "r"(pair + 1), "r"(64) : "memory");
        float eo[2][2][4];              // other half's batches
#pragma unroll
        for (int ob = 0; ob < 2; ob++) {
            int b = (1 - half) * 2 + ob;
#pragma unroll
            for (int mg = 0; mg < 2; mg++)
#pragma unroll
                for (int r = 0; r < 4; r++)
                    eo[ob][mg][r] = ex[((pair * 4 + b) * 8 + mg * 4 + r) * 32 + l];
        }

        // ------------- softmax over batch; pack P once as fp16 -------------
        uint32_t pH[2][4];
#pragma unroll
        for (int mg = 0; mg < 2; mg++)
#pragma unroll
            for (int rp = 0; rp < 2; rp++) {
                int a = mg * 2 + rp;
                float s0 = e[0][mg][rp*2]   + e[1][mg][rp*2]
                         + eo[0][mg][rp*2]  + eo[1][mg][rp*2];
                float s1 = e[0][mg][rp*2+1] + e[1][mg][rp*2+1]
                         + eo[0][mg][rp*2+1] + eo[1][mg][rp*2+1];
                float i0 = __fdividef(1.f, s0), i1 = __fdividef(1.f, s1);
#pragma unroll
                for (int ob = 0; ob < 2; ob++)
                    pH[ob][a] = pk_f16x2(e[ob][mg][rp*2] * i0,
                                         e[ob][mg][rp*2+1] * i1);
            }

        // ------------- PV: Y_ob += Ph_ob * Vh_b (single term) -------------
#pragma unroll
        for (int ob = 0; ob < 2; ob++) {
            int b = half * 2 + ob;
            uint32_t vh[2][4];
            uint32_t vb = sbV + b * 5120 + rpk;
            ldsm4t(vh[0], vb);          ldsm4t(vh[1], vb + 32);
#pragma unroll
            for (int cg = 0; cg < 4; cg++) {
                uint32_t bh0 = vh[cg >> 1][(cg & 1) * 2];
                uint32_t bh1 = vh[cg >> 1][(cg & 1) * 2 + 1];
                mma16816(Y[ob][cg], pH[ob], bh0, bh1);
            }
        }
    }

    // ---- cross-wm reduction of partial Y, then write ----
    __syncthreads();                    // all warps done with K/V smem
    float* red = (float*)smc;           // 16w x 32e x 32 lanes = 64 KB
#pragma unroll
    for (int ob = 0; ob < 2; ob++)
#pragma unroll
        for (int cg = 0; cg < 4; cg++)
#pragma unroll
            for (int r = 0; r < 4; r++)
                red[(w * 32 + ob * 16 + cg * 4 + r) * 32 + l] = Y[ob][cg][r];
    __syncthreads();
    {
        // task: warp w reduces (wn_r, batch rb, cg-half cgh) over wm 0..3
        int wn_r = w >> 3, rb = (w >> 1) & 3, cgh = w & 1;
        int sh = rb >> 1, sob = rb & 1;  // source half, source ob slot
        float o[2][4];
#pragma unroll
        for (int cgi = 0; cgi < 2; cgi++) {
            int cg = cgh * 2 + cgi;
#pragma unroll
            for (int r = 0; r < 4; r++) {
                int e2 = sob * 16 + cg * 4 + r;
                o[cgi][r] =
                      red[((wn_r * 8 + 0 * 2 + sh) * 32 + e2) * 32 + l]
                    + red[((wn_r * 8 + 1 * 2 + sh) * 32 + e2) * 32 + l]
                    + red[((wn_r * 8 + 2 * 2 + sh) * 32 + e2) * 32 + l]
                    + red[((wn_r * 8 + 3 * 2 + sh) * 32 + e2) * 32 + l];
            }
        }
        int n = n0 + wn_r * 16 + g;
#pragma unroll
        for (int cgi = 0; cgi < 2; cgi++) {
            int cg = cgh * 2 + cgi;
            int cc = cg * 8 + tg * 2;
            *(float2*)(gY + rb * BS + n * CH + cc) =
                make_float2(o[cgi][0], o[cgi][1]);
            *(float2*)(gY + rb * BS + (n + 8) * CH + cc) =
                make_float2(o[cgi][2], o[cgi][3]);
        }
    }
}

// ---------------------------------------------------------------------------
// Kernel 3: final 1x1 conv (32->64). gY flat == y2[b][ci][hw].
// ---------------------------------------------------------------------------
__global__ __launch_bounds__(256) void outconv_kernel(
    const float* __restrict__ w4, const float* __restrict__ b4,
    float* __restrict__ out)
{
    __shared__ float ws[16 * CH];
    __shared__ float bsm[16];
    int t = threadIdx.x;
    int cob = blockIdx.y * 16;
    for (int i = t; i < 16 * CH; i += 256) ws[i] = w4[cob * CH + i];
    if (t < 16) bsm[t] = b4[cob + t];
    __syncthreads();

    int idx = blockIdx.x * 256 + t;
    int b = idx >> 12, hw = idx & 4095;
    const float* yp = gY + b * BS + hw;

    float acc[16];
#pragma unroll
    for (int co = 0; co < 16; co++) acc[co] = bsm[co];

#pragma unroll 8
    for (int ci = 0; ci < CH; ci++) {
        float yv = yp[ci * NFLAT];
#pragma unroll
        for (int co = 0; co < 16; co++) acc[co] += ws[co * CH + ci] * yv;
    }

    float* op = out + b * (CIN * NFLAT) + cob * NFLAT + hw;
#pragma unroll
    for (int co = 0; co < 16; co++) op[co * NFLAT] = acc[co];
}

// ---------------------------------------------------------------------------
extern "C" void kernel_launch(void* const* d_in, const int* in_sizes, int n_in,
                              void* d_out, int out_size)
{
    const float* x  = (const float*)d_in[0];
    const float* w1 = (const float*)d_in[1];
    const float* b1 = (const float*)d_in[2];
    const float* w2 = (const float*)d_in[3];
    const float* b2 = (const float*)d_in[4];
    const float* w3 = (const float*)d_in[5];
    const float* b3 = (const float*)d_in[6];
    const float* w4 = (const float*)d_in[7];
    const float* b4 = (const float*)d_in[8];
    float* out = (float*)d_out;

    cudaFuncSetAttribute(attn_kernel,
                         cudaFuncAttributeMaxDynamicSharedMemorySize, SMB);

    qkv_kernel<<<dim3(64, 3, 4), 256>>>(x, w1, b1, w2, b2, w3, b3);
    attn_kernel<<<128, 512, SMB>>>();
    outconv_kernel<<<dim3(64, 4), 256>>>(w4, b4, out);
}